// round 1
// baseline (speedup 1.0000x reference)
#include <cuda_runtime.h>
#include <math.h>

#define N_NODES   50000
#define N_EDGES   800000
#define NUM_GRAPHS 256
#define HDIM      128
#define C         129     // CGConv channels
#define ZDIM      259     // 2*C + 1
#define NLAYERS   5
#define KP        264     // padded K
#define NP        264     // padded N (2 * 132, f/s interleaved)
#define TM        32      // edges per CTA
#define KC        12      // K chunk staged in smem
#define NT        264     // threads per CTA (8 x 33)

// ---------------- device scratch (static, no allocations) ----------------
__device__ float d_xa[N_NODES * C];
__device__ float d_xb[N_NODES * C];
__device__ float d_ea[N_EDGES];
__device__ float d_wpack[NLAYERS * KP * NP];
__device__ float d_bpack[NLAYERS * NP];
__device__ float d_gsum[NUM_GRAPHS * C];
__device__ float d_gcnt[NUM_GRAPHS];

// ---------------- weight packing: interleave Wf/Ws columns, zero-pad ------
__global__ void pack_w_kernel(const float* __restrict__ Wf,
                              const float* __restrict__ Ws) {
    int idx = blockIdx.x * blockDim.x + threadIdx.x;
    if (idx >= NLAYERS * KP * NP) return;
    int col = idx % NP;
    int kp  = (idx / NP) % KP;
    int l   = idx / (NP * KP);
    int j   = col >> 1;
    float v = 0.f;
    if (kp < ZDIM && j < C) {
        const float* W = (col & 1) ? Ws : Wf;
        v = W[(l * ZDIM + kp) * C + j];
    }
    d_wpack[idx] = v;
}

__global__ void pack_b_kernel(const float* __restrict__ bf,
                              const float* __restrict__ bs) {
    int idx = blockIdx.x * blockDim.x + threadIdx.x;
    if (idx >= NLAYERS * NP) return;
    int col = idx % NP;
    int l   = idx / NP;
    int j   = col >> 1;
    float v = 0.f;
    if (j < C) v = (col & 1) ? bs[l * C + j] : bf[l * C + j];
    d_bpack[idx] = v;
}

// ---------------- node feature init: emb[atoms] || pos.z -----------------
__global__ void init_x_kernel(const int* __restrict__ atoms,
                              const float* __restrict__ pos,
                              const float* __restrict__ emb) {
    int idx = blockIdx.x * blockDim.x + threadIdx.x;
    if (idx >= N_NODES * C) return;
    int n = idx / C;
    int c = idx - n * C;
    d_xa[idx] = (c < HDIM) ? emb[atoms[n] * HDIM + c] : pos[n * 3 + 2];
}

// ---------------- edge attribute: ||pos[src]-pos[dst]|| ------------------
__global__ void ea_kernel(const int* __restrict__ ei,
                          const float* __restrict__ pos) {
    int e = blockIdx.x * blockDim.x + threadIdx.x;
    if (e >= N_EDGES) return;
    int s = ei[e];
    int d = ei[N_EDGES + e];
    float dx = pos[s * 3 + 0] - pos[d * 3 + 0];
    float dy = pos[s * 3 + 1] - pos[d * 3 + 1];
    float dz = pos[s * 3 + 2] - pos[d * 3 + 2];
    d_ea[e] = sqrtf(dx * dx + dy * dy + dz * dz);
}

// ---------------- residual copy (x_next = x_cur) --------------------------
__global__ void copy4_kernel(const float4* __restrict__ a,
                             float4* __restrict__ b, int n4) {
    int i = blockIdx.x * blockDim.x + threadIdx.x;
    if (i < n4) b[i] = a[i];
}

// ---------------- fused edge GEMM + gate + scatter -------------------------
// CTA: 32 edges x 258 outputs (f/s interleaved). z rows staged fully in smem,
// W staged in K-chunks. Thread (mr,nc): 4 edges x 8 cols = 4 (f,s) pairs.
__global__ __launch_bounds__(NT)
void edge_gemm_kernel(const float* __restrict__ xc,
                      float* __restrict__ xn,
                      const int* __restrict__ ei,
                      int layer) {
    __shared__ float z_s[TM * KP];      // 33792 B
    __shared__ float w_s[KC * NP];      // 12672 B
    __shared__ int dst_s[TM], src_s[TM];

    int tid = threadIdx.x;
    int e0  = blockIdx.x * TM;

    if (tid < TM) {
        src_s[tid] = ei[e0 + tid];
        dst_s[tid] = ei[N_EDGES + e0 + tid];
    }
    __syncthreads();

    // Gather z rows: z = [x[dst](129) | x[src](129) | ea(1) | 0-pad]
    {
        int kk = tid;  // NT == KP, each thread owns one k column
        if (kk < C) {
            #pragma unroll 4
            for (int r = 0; r < TM; r++)
                z_s[r * KP + kk] = xc[dst_s[r] * C + kk];
        } else if (kk < 2 * C) {
            int k2 = kk - C;
            #pragma unroll 4
            for (int r = 0; r < TM; r++)
                z_s[r * KP + kk] = xc[src_s[r] * C + k2];
        } else if (kk == 2 * C) {
            for (int r = 0; r < TM; r++)
                z_s[r * KP + kk] = d_ea[e0 + r];
        } else {
            for (int r = 0; r < TM; r++)
                z_s[r * KP + kk] = 0.f;
        }
    }

    int mr = tid / 33;   // 0..7 : edge group (4 edges)
    int nc = tid % 33;   // 0..32: column group (8 cols = 4 f/s pairs)

    float acc[4][8];
    #pragma unroll
    for (int i = 0; i < 4; i++)
        #pragma unroll
        for (int j = 0; j < 8; j++) acc[i][j] = 0.f;

    const float* wl = d_wpack + layer * (KP * NP);

    for (int k0 = 0; k0 < KP; k0 += KC) {
        __syncthreads();
        #pragma unroll
        for (int r = 0; r < KC; r++)
            w_s[r * NP + tid] = wl[(k0 + r) * NP + tid];
        __syncthreads();

        #pragma unroll
        for (int k4 = 0; k4 < KC; k4 += 4) {
            float4 zf[4];
            #pragma unroll
            for (int i = 0; i < 4; i++)
                zf[i] = *(const float4*)&z_s[(mr * 4 + i) * KP + k0 + k4];
            #pragma unroll
            for (int t = 0; t < 4; t++) {
                float4 wa = *(const float4*)&w_s[(k4 + t) * NP + nc * 8];
                float4 wb = *(const float4*)&w_s[(k4 + t) * NP + nc * 8 + 4];
                #pragma unroll
                for (int i = 0; i < 4; i++) {
                    float zv = ((const float*)&zf[i])[t];
                    acc[i][0] = fmaf(zv, wa.x, acc[i][0]);
                    acc[i][1] = fmaf(zv, wa.y, acc[i][1]);
                    acc[i][2] = fmaf(zv, wa.z, acc[i][2]);
                    acc[i][3] = fmaf(zv, wa.w, acc[i][3]);
                    acc[i][4] = fmaf(zv, wb.x, acc[i][4]);
                    acc[i][5] = fmaf(zv, wb.y, acc[i][5]);
                    acc[i][6] = fmaf(zv, wb.z, acc[i][6]);
                    acc[i][7] = fmaf(zv, wb.w, acc[i][7]);
                }
            }
        }
    }

    // Epilogue: m = sigmoid(f) * softplus(s), scatter-add at dst
    const float* bl = d_bpack + layer * NP;
    #pragma unroll
    for (int i = 0; i < 4; i++) {
        float* xrow = xn + (long)dst_s[mr * 4 + i] * C;
        #pragma unroll
        for (int t = 0; t < 4; t++) {
            int ch = nc * 4 + t;
            if (ch < C) {
                float f = acc[i][2 * t]     + bl[2 * ch];
                float s = acc[i][2 * t + 1] + bl[2 * ch + 1];
                float sg = 1.f / (1.f + expf(-f));
                float sp = fmaxf(s, 0.f) + log1pf(expf(-fabsf(s)));
                atomicAdd(xrow + ch, sg * sp);
            }
        }
    }
}

// ---------------- pooling ----------------------------------------------
__global__ void zero_pool_kernel() {
    int idx = blockIdx.x * blockDim.x + threadIdx.x;
    if (idx < NUM_GRAPHS * C) d_gsum[idx] = 0.f;
    if (idx < NUM_GRAPHS)     d_gcnt[idx] = 0.f;
}

__global__ void pool_kernel(const float* __restrict__ x,
                            const int* __restrict__ batch) {
    int idx = blockIdx.x * blockDim.x + threadIdx.x;
    if (idx >= N_NODES * C) return;
    int n = idx / C;
    int c = idx - n * C;
    int b = batch[n];
    atomicAdd(&d_gsum[b * C + c], x[idx]);
    if (c == 0) atomicAdd(&d_gcnt[b], 1.f);
}

// ---------------- FC head: 3 layers + output ---------------------------
__global__ void head_kernel(const float* __restrict__ Wfc,
                            const float* __restrict__ bfc,
                            const float* __restrict__ Wout,
                            const float* __restrict__ bout,
                            float* __restrict__ out) {
    int g = blockIdx.x;
    int t = threadIdx.x;  // 256 threads
    __shared__ float row[C];
    __shared__ float red[256];

    if (t < C) row[t] = d_gsum[g * C + t] / fmaxf(d_gcnt[g], 1.f);
    __syncthreads();

    for (int l = 0; l < 3; l++) {
        float y = 0.f;
        if (t < C) {
            #pragma unroll 4
            for (int k = 0; k < C; k++)
                y = fmaf(row[k], Wfc[(l * C + k) * C + t], y);
            y += bfc[l * C + t];
        }
        __syncthreads();
        if (t < C) row[t] = y;
        __syncthreads();
    }

    red[t] = (t < C) ? row[t] * Wout[t] : 0.f;
    __syncthreads();
    for (int s = 128; s > 0; s >>= 1) {
        if (t < s) red[t] += red[t + s];
        __syncthreads();
    }
    if (t == 0) out[g] = red[0] + bout[0];
}

// ---------------- launch -------------------------------------------------
extern "C" void kernel_launch(void* const* d_in, const int* in_sizes, int n_in,
                              void* d_out, int out_size) {
    const int*   atoms = (const int*)d_in[0];
    const float* pos   = (const float*)d_in[1];
    const int*   ei    = (const int*)d_in[2];
    const int*   batch = (const int*)d_in[3];
    const float* emb   = (const float*)d_in[4];
    const float* Wf    = (const float*)d_in[5];
    const float* bf    = (const float*)d_in[6];
    const float* Ws    = (const float*)d_in[7];
    const float* bs    = (const float*)d_in[8];
    const float* Wfc   = (const float*)d_in[9];
    const float* bfc   = (const float*)d_in[10];
    const float* Wout  = (const float*)d_in[11];
    const float* bout  = (const float*)d_in[12];
    float* out = (float*)d_out;

    float *xa, *xb;
    cudaGetSymbolAddress((void**)&xa, d_xa);
    cudaGetSymbolAddress((void**)&xb, d_xb);

    pack_w_kernel<<<(NLAYERS * KP * NP + 255) / 256, 256>>>(Wf, Ws);
    pack_b_kernel<<<(NLAYERS * NP + 255) / 256, 256>>>(bf, bs);
    init_x_kernel<<<(N_NODES * C + 255) / 256, 256>>>(atoms, pos, emb);
    ea_kernel<<<(N_EDGES + 255) / 256, 256>>>(ei, pos);

    const int n4 = (N_NODES * C) / 4;  // 6450000 divisible by 4
    float* cur = xa;
    float* nxt = xb;
    for (int l = 0; l < NLAYERS; l++) {
        copy4_kernel<<<(n4 + 255) / 256, 256>>>((const float4*)cur,
                                                (float4*)nxt, n4);
        edge_gemm_kernel<<<N_EDGES / TM, NT>>>(cur, nxt, ei, l);
        float* tmp = cur; cur = nxt; nxt = tmp;
    }

    zero_pool_kernel<<<(NUM_GRAPHS * C + 255) / 256, 256>>>();
    pool_kernel<<<(N_NODES * C + 255) / 256, 256>>>(cur, batch);
    head_kernel<<<NUM_GRAPHS, 256>>>(Wfc, bfc, Wout, bout, out);
}

// round 2
// speedup vs baseline: 1.0554x; 1.0554x over previous
#include <cuda_runtime.h>
#include <math.h>

#define N_NODES   50000
#define N_EDGES   800000
#define NUM_GRAPHS 256
#define HDIM      128
#define C         129     // CGConv channels
#define ZDIM      259     // 2*C + 1
#define NLAYERS   5
#define KP        264     // padded K
#define NP        264     // padded N (2 * 132, f/s interleaved)
#define TM        32      // edges per CTA
#define KC        12      // K chunk staged in smem
#define NT        264     // threads per CTA (8 x 33)

// ---------------- device scratch (static, no allocations) ----------------
__device__ float d_xa[N_NODES * C];
__device__ float d_xb[N_NODES * C];
__device__ float d_ea[N_EDGES];
__device__ float d_wpack[NLAYERS * KP * NP];
__device__ float d_bpack[NLAYERS * NP];
__device__ float d_gsum[NUM_GRAPHS * C];
__device__ float d_gcnt[NUM_GRAPHS];

// ---------------- weight packing: interleave Wf/Ws columns, zero-pad ------
__global__ void pack_w_kernel(const float* __restrict__ Wf,
                              const float* __restrict__ Ws) {
    int idx = blockIdx.x * blockDim.x + threadIdx.x;
    if (idx >= NLAYERS * KP * NP) return;
    int col = idx % NP;
    int kp  = (idx / NP) % KP;
    int l   = idx / (NP * KP);
    int j   = col >> 1;
    float v = 0.f;
    if (kp < ZDIM && j < C) {
        const float* W = (col & 1) ? Ws : Wf;
        v = W[(l * ZDIM + kp) * C + j];
    }
    d_wpack[idx] = v;
}

__global__ void pack_b_kernel(const float* __restrict__ bf,
                              const float* __restrict__ bs) {
    int idx = blockIdx.x * blockDim.x + threadIdx.x;
    if (idx >= NLAYERS * NP) return;
    int col = idx % NP;
    int l   = idx / NP;
    int j   = col >> 1;
    float v = 0.f;
    if (j < C) v = (col & 1) ? bs[l * C + j] : bf[l * C + j];
    d_bpack[idx] = v;
}

// ---------------- node feature init: emb[atoms] || pos.z -----------------
__global__ void init_x_kernel(const int* __restrict__ atoms,
                              const float* __restrict__ pos,
                              const float* __restrict__ emb) {
    int idx = blockIdx.x * blockDim.x + threadIdx.x;
    if (idx >= N_NODES * C) return;
    int n = idx / C;
    int c = idx - n * C;
    d_xa[idx] = (c < HDIM) ? emb[atoms[n] * HDIM + c] : pos[n * 3 + 2];
}

// ---------------- edge attribute: ||pos[src]-pos[dst]|| ------------------
__global__ void ea_kernel(const int* __restrict__ ei,
                          const float* __restrict__ pos) {
    int e = blockIdx.x * blockDim.x + threadIdx.x;
    if (e >= N_EDGES) return;
    int s = ei[e];
    int d = ei[N_EDGES + e];
    float dx = pos[s * 3 + 0] - pos[d * 3 + 0];
    float dy = pos[s * 3 + 1] - pos[d * 3 + 1];
    float dz = pos[s * 3 + 2] - pos[d * 3 + 2];
    d_ea[e] = sqrtf(dx * dx + dy * dy + dz * dz);
}

// ---------------- residual copy (x_next = x_cur) --------------------------
__global__ void copy4_kernel(const float4* __restrict__ a,
                             float4* __restrict__ b, int n4) {
    int i = blockIdx.x * blockDim.x + threadIdx.x;
    if (i < n4) b[i] = a[i];
}

// ---------------- fused edge GEMM + gate + scatter -------------------------
// CTA: 32 edges x 258 outputs (f/s interleaved). z rows staged fully in smem,
// W staged in K-chunks. Thread (mr,nc): 4 edges x 8 cols = 4 (f,s) pairs.
__global__ __launch_bounds__(NT)
void edge_gemm_kernel(const float* __restrict__ xc,
                      float* __restrict__ xn,
                      const int* __restrict__ ei,
                      int layer) {
    __shared__ float z_s[TM * KP];      // 33792 B
    __shared__ float w_s[KC * NP];      // 12672 B
    __shared__ int dst_s[TM], src_s[TM];

    int tid = threadIdx.x;
    int e0  = blockIdx.x * TM;

    if (tid < TM) {
        src_s[tid] = ei[e0 + tid];
        dst_s[tid] = ei[N_EDGES + e0 + tid];
    }
    __syncthreads();

    // Gather z rows: z = [x[dst](129) | x[src](129) | ea(1) | 0-pad]
    {
        int kk = tid;  // NT == KP, each thread owns one k column
        if (kk < C) {
            #pragma unroll 4
            for (int r = 0; r < TM; r++)
                z_s[r * KP + kk] = xc[dst_s[r] * C + kk];
        } else if (kk < 2 * C) {
            int k2 = kk - C;
            #pragma unroll 4
            for (int r = 0; r < TM; r++)
                z_s[r * KP + kk] = xc[src_s[r] * C + k2];
        } else if (kk == 2 * C) {
            for (int r = 0; r < TM; r++)
                z_s[r * KP + kk] = d_ea[e0 + r];
        } else {
            for (int r = 0; r < TM; r++)
                z_s[r * KP + kk] = 0.f;
        }
    }

    int mr = tid / 33;   // 0..7 : edge group (4 edges)
    int nc = tid % 33;   // 0..32: column group (8 cols = 4 f/s pairs)

    float acc[4][8];
    #pragma unroll
    for (int i = 0; i < 4; i++)
        #pragma unroll
        for (int j = 0; j < 8; j++) acc[i][j] = 0.f;

    const float* wl = d_wpack + layer * (KP * NP);

    for (int k0 = 0; k0 < KP; k0 += KC) {
        __syncthreads();
        #pragma unroll
        for (int r = 0; r < KC; r++)
            w_s[r * NP + tid] = wl[(k0 + r) * NP + tid];
        __syncthreads();

        #pragma unroll
        for (int k4 = 0; k4 < KC; k4 += 4) {
            float4 zf[4];
            #pragma unroll
            for (int i = 0; i < 4; i++)
                zf[i] = *(const float4*)&z_s[(mr * 4 + i) * KP + k0 + k4];
            #pragma unroll
            for (int t = 0; t < 4; t++) {
                float4 wa = *(const float4*)&w_s[(k4 + t) * NP + nc * 8];
                float4 wb = *(const float4*)&w_s[(k4 + t) * NP + nc * 8 + 4];
                #pragma unroll
                for (int i = 0; i < 4; i++) {
                    float zv = ((const float*)&zf[i])[t];
                    acc[i][0] = fmaf(zv, wa.x, acc[i][0]);
                    acc[i][1] = fmaf(zv, wa.y, acc[i][1]);
                    acc[i][2] = fmaf(zv, wa.z, acc[i][2]);
                    acc[i][3] = fmaf(zv, wa.w, acc[i][3]);
                    acc[i][4] = fmaf(zv, wb.x, acc[i][4]);
                    acc[i][5] = fmaf(zv, wb.y, acc[i][5]);
                    acc[i][6] = fmaf(zv, wb.z, acc[i][6]);
                    acc[i][7] = fmaf(zv, wb.w, acc[i][7]);
                }
            }
        }
    }

    // Epilogue: m = sigmoid(f) * softplus(s), scatter-add at dst
    const float* bl = d_bpack + layer * NP;
    #pragma unroll
    for (int i = 0; i < 4; i++) {
        float* xrow = xn + (long)dst_s[mr * 4 + i] * C;
        #pragma unroll
        for (int t = 0; t < 4; t++) {
            int ch = nc * 4 + t;
            if (ch < C) {
                float f = acc[i][2 * t]     + bl[2 * ch];
                float s = acc[i][2 * t + 1] + bl[2 * ch + 1];
                float sg = 1.f / (1.f + expf(-f));
                float sp = fmaxf(s, 0.f) + log1pf(expf(-fabsf(s)));
                atomicAdd(xrow + ch, sg * sp);
            }
        }
    }
}

// ---------------- pooling ----------------------------------------------
__global__ void zero_pool_kernel() {
    int idx = blockIdx.x * blockDim.x + threadIdx.x;
    if (idx < NUM_GRAPHS * C) d_gsum[idx] = 0.f;
    if (idx < NUM_GRAPHS)     d_gcnt[idx] = 0.f;
}

__global__ void pool_kernel(const float* __restrict__ x,
                            const int* __restrict__ batch) {
    int idx = blockIdx.x * blockDim.x + threadIdx.x;
    if (idx >= N_NODES * C) return;
    int n = idx / C;
    int c = idx - n * C;
    int b = batch[n];
    atomicAdd(&d_gsum[b * C + c], x[idx]);
    if (c == 0) atomicAdd(&d_gcnt[b], 1.f);
}

// ---------------- FC head: 3 layers + output ---------------------------
__global__ void head_kernel(const float* __restrict__ Wfc,
                            const float* __restrict__ bfc,
                            const float* __restrict__ Wout,
                            const float* __restrict__ bout,
                            float* __restrict__ out) {
    int g = blockIdx.x;
    int t = threadIdx.x;  // 256 threads
    __shared__ float row[C];
    __shared__ float red[256];

    if (t < C) row[t] = d_gsum[g * C + t] / fmaxf(d_gcnt[g], 1.f);
    __syncthreads();

    for (int l = 0; l < 3; l++) {
        float y = 0.f;
        if (t < C) {
            #pragma unroll 4
            for (int k = 0; k < C; k++)
                y = fmaf(row[k], Wfc[(l * C + k) * C + t], y);
            y += bfc[l * C + t];
        }
        __syncthreads();
        if (t < C) row[t] = y;
        __syncthreads();
    }

    red[t] = (t < C) ? row[t] * Wout[t] : 0.f;
    __syncthreads();
    for (int s = 128; s > 0; s >>= 1) {
        if (t < s) red[t] += red[t + s];
        __syncthreads();
    }
    if (t == 0) out[g] = red[0] + bout[0];
}

// ---------------- launch -------------------------------------------------
extern "C" void kernel_launch(void* const* d_in, const int* in_sizes, int n_in,
                              void* d_out, int out_size) {
    const int*   atoms = (const int*)d_in[0];
    const float* pos   = (const float*)d_in[1];
    const int*   ei    = (const int*)d_in[2];
    const int*   batch = (const int*)d_in[3];
    const float* emb   = (const float*)d_in[4];
    const float* Wf    = (const float*)d_in[5];
    const float* bf    = (const float*)d_in[6];
    const float* Ws    = (const float*)d_in[7];
    const float* bs    = (const float*)d_in[8];
    const float* Wfc   = (const float*)d_in[9];
    const float* bfc   = (const float*)d_in[10];
    const float* Wout  = (const float*)d_in[11];
    const float* bout  = (const float*)d_in[12];
    float* out = (float*)d_out;

    float *xa, *xb;
    cudaGetSymbolAddress((void**)&xa, d_xa);
    cudaGetSymbolAddress((void**)&xb, d_xb);

    pack_w_kernel<<<(NLAYERS * KP * NP + 255) / 256, 256>>>(Wf, Ws);
    pack_b_kernel<<<(NLAYERS * NP + 255) / 256, 256>>>(bf, bs);
    init_x_kernel<<<(N_NODES * C + 255) / 256, 256>>>(atoms, pos, emb);
    ea_kernel<<<(N_EDGES + 255) / 256, 256>>>(ei, pos);

    const int n4 = (N_NODES * C) / 4;  // 6450000 divisible by 4
    float* cur = xa;
    float* nxt = xb;
    for (int l = 0; l < NLAYERS; l++) {
        copy4_kernel<<<(n4 + 255) / 256, 256>>>((const float4*)cur,
                                                (float4*)nxt, n4);
        edge_gemm_kernel<<<N_EDGES / TM, NT>>>(cur, nxt, ei, l);
        float* tmp = cur; cur = nxt; nxt = tmp;
    }

    zero_pool_kernel<<<(NUM_GRAPHS * C + 255) / 256, 256>>>();
    pool_kernel<<<(N_NODES * C + 255) / 256, 256>>>(cur, batch);
    head_kernel<<<NUM_GRAPHS, 256>>>(Wfc, bfc, Wout, bout, out);
}

// round 4
// speedup vs baseline: 3.2384x; 3.0683x over previous
#include <cuda_runtime.h>
#include <cuda_bf16.h>
#include <cstdint>
#include <math.h>

#define N_NODES   50000
#define N_EDGES   800000
#define NUM_GRAPHS 256
#define C         129
#define ZDIM      259
#define NLAYERS   5
#define XS        132      // padded x row stride (floats)
#define NPAD      288      // padded interleaved cols for GEMM (144 f/s pairs)
#define NB        264      // bias/tail col count (132 pairs)

// smem byte offsets
#define SA    0            // A hi: 128 rows x 264 bf16 (stride 528B) = 67584
#define SAL   67584        // A lo
#define SB    135168       // B: 2 bufs x (2 splits x 288 x 40 bf16)
#define SBUF  46080
#define SSP   23040
#define STL   227328       // tails: 3 x 128 f32
#define SBI   228864       // bias: 264 f32
#define SDS   229920       // dst: 128 int
#define SSR   230432       // src: 128 int
#define SMEM_TOTAL 230944

__device__ __align__(16) __nv_bfloat16 d_wb2[NLAYERS * 2 * NPAD * 256];
__device__ float d_wt3[NLAYERS * 3 * NB];
__device__ float d_bp[NLAYERS * NB];
__device__ __align__(16) float d_xa[N_NODES * XS];
__device__ __align__(16) float d_xb[N_NODES * XS];
__device__ float d_ea[N_EDGES];
__device__ float d_gsum[NUM_GRAPHS * C];
__device__ float d_gcnt[NUM_GRAPHS];

__device__ __forceinline__ uint32_t smem_u32(const void* p) {
    uint32_t a;
    asm("{ .reg .u64 t; cvta.to.shared.u64 t, %1; cvt.u32.u64 %0, t; }" : "=r"(a) : "l"(p));
    return a;
}
__device__ __forceinline__ void mma16816(float* d, uint32_t a0, uint32_t a1,
                                         uint32_t a2, uint32_t a3,
                                         uint32_t b0, uint32_t b1) {
    asm volatile(
        "mma.sync.aligned.m16n8k16.row.col.f32.bf16.bf16.f32 "
        "{%0,%1,%2,%3}, {%4,%5,%6,%7}, {%8,%9}, {%0,%1,%2,%3};"
        : "+f"(d[0]), "+f"(d[1]), "+f"(d[2]), "+f"(d[3])
        : "r"(a0), "r"(a1), "r"(a2), "r"(a3), "r"(b0), "r"(b1));
}
__device__ __forceinline__ void cpasync16(uint32_t s, const void* g) {
    asm volatile("cp.async.cg.shared.global [%0], [%1], 16;" :: "r"(s), "l"(g));
}
__device__ __forceinline__ void red4(float* p, float4 v) {
    asm volatile("red.global.add.v4.f32 [%0], {%1,%2,%3,%4};"
                 :: "l"(p), "f"(v.x), "f"(v.y), "f"(v.z), "f"(v.w) : "memory");
}

// ---- prepack W: [l][split][n 288][k 256] bf16, hi/lo split ----
__global__ void pack_wb_kernel(const float* __restrict__ Wf, const float* __restrict__ Ws) {
    int idx = blockIdx.x * blockDim.x + threadIdx.x;
    if (idx >= NLAYERS * 2 * NPAD * 256) return;
    int k  = idx & 255;
    int n  = (idx >> 8) % NPAD;
    int sp = (idx / (256 * NPAD)) & 1;
    int l  = idx / (256 * NPAD * 2);
    int j = n >> 1;
    int zi = (k < 128) ? k : (k + 1);          // x_dst[0:128] then x_src[0:128]
    float w = 0.f;
    if (j < C) { const float* W = (n & 1) ? Ws : Wf; w = W[(l * ZDIM + zi) * C + j]; }
    __nv_bfloat16 hi = __float2bfloat16(w);
    __nv_bfloat16 v = sp ? __float2bfloat16(w - __bfloat162float(hi)) : hi;
    d_wb2[idx] = v;
}
// tail rows zi = {128, 257, 258} (fp32 exact)
__global__ void pack_tail_kernel(const float* __restrict__ Wf, const float* __restrict__ Ws) {
    int idx = blockIdx.x * blockDim.x + threadIdx.x;
    if (idx >= NLAYERS * 3 * NB) return;
    int n = idx % NB, t = (idx / NB) % 3, l = idx / (3 * NB);
    int j = n >> 1, zi = (t == 0) ? 128 : (t == 1 ? 257 : 258);
    float w = 0.f;
    if (j < C) { const float* W = (n & 1) ? Ws : Wf; w = W[(l * ZDIM + zi) * C + j]; }
    d_wt3[idx] = w;
}
__global__ void pack_bias_kernel(const float* __restrict__ bf, const float* __restrict__ bs) {
    int idx = blockIdx.x * blockDim.x + threadIdx.x;
    if (idx >= NLAYERS * NB) return;
    int n = idx % NB, l = idx / NB, j = n >> 1;
    float v = 0.f;
    if (j < C) v = (n & 1) ? bs[l * C + j] : bf[l * C + j];
    d_bp[idx] = v;
}
__global__ void init_x_kernel(const int* __restrict__ atoms, const float* __restrict__ pos,
                              const float* __restrict__ emb) {
    int idx = blockIdx.x * blockDim.x + threadIdx.x;
    if (idx >= N_NODES * XS) return;
    int n = idx / XS, c = idx - n * XS;
    float v = 0.f;
    if (c < 128) v = emb[atoms[n] * 128 + c];
    else if (c == 128) v = pos[n * 3 + 2];
    d_xa[idx] = v;
}
__global__ void ea_kernel(const int* __restrict__ ei, const float* __restrict__ pos) {
    int e = blockIdx.x * blockDim.x + threadIdx.x;
    if (e >= N_EDGES) return;
    int s = ei[e], d = ei[N_EDGES + e];
    float dx = pos[s*3]-pos[d*3], dy = pos[s*3+1]-pos[d*3+1], dz = pos[s*3+2]-pos[d*3+2];
    d_ea[e] = sqrtf(dx*dx + dy*dy + dz*dz);
}
__global__ void copy4_kernel(const float4* __restrict__ a, float4* __restrict__ b, int n4) {
    int i = blockIdx.x * blockDim.x + threadIdx.x;
    if (i < n4) b[i] = a[i];
}

// ---- fused bf16 mma.sync edge GEMM + gate + vector scatter ----
__global__ __launch_bounds__(512, 1)
void edge_mma_kernel(const float* __restrict__ xc, float* __restrict__ xn,
                     const int* __restrict__ ei, int layer) {
    extern __shared__ __align__(16) char smem[];
    uint32_t sb = smem_u32(smem);
    int tid = threadIdx.x, lane = tid & 31, wid = tid >> 5;
    int r0 = lane >> 2, tin = lane & 3, kc2 = tin * 2;
    int warpM = wid & 3, warpN = wid >> 2;
    int e0 = blockIdx.x * 128;

    int*   dstS = (int*)(smem + SDS);
    int*   srcS = (int*)(smem + SSR);
    float* tlS  = (float*)(smem + STL);
    float* biS  = (float*)(smem + SBI);

    const __nv_bfloat16* wbase = d_wb2 + (size_t)layer * 2 * NPAD * 256;

    // B prologue sub-chunks 0,1 (independent of smem state)
    #pragma unroll
    for (int pc = 0; pc < 2; pc++) {
        for (int i = tid; i < 2304; i += 512) {
            int sp = i / 1152, rr = i % 1152, n = rr >> 2, kv = rr & 3;
            const void* g = wbase + ((size_t)sp * NPAD + n) * 256 + pc * 32 + kv * 8;
            cpasync16(sb + SB + pc * SBUF + sp * SSP + n * 80 + kv * 16, g);
        }
        asm volatile("cp.async.commit_group;" ::: "memory");
    }

    if (tid < 128) {
        int e = e0 + tid, s_ = ei[e], d_ = ei[N_EDGES + e];
        srcS[tid] = s_; dstS[tid] = d_;
        tlS[tid]       = xc[(size_t)d_ * XS + 128];
        tlS[128 + tid] = xc[(size_t)s_ * XS + 128];
        tlS[256 + tid] = d_ea[e];
    }
    for (int i = tid; i < NB; i += 512) biS[i] = d_bp[layer * NB + i];
    __syncthreads();

    // gather + hi/lo bf16 convert A: thread = (edge m=tid>>2, quarter q=tid&3)
    {
        int m = tid >> 2, q = tid & 3;
        int node = (q < 2) ? dstS[m] : srcS[m];
        const float4* xr = (const float4*)(xc + (size_t)node * XS) + (q & 1) * 16;
        char* arow = smem + SA + m * 528 + q * 128;
        #pragma unroll
        for (int j = 0; j < 16; j++) {
            float4 v = xr[j];
            __nv_bfloat16 hx = __float2bfloat16(v.x), hy = __float2bfloat16(v.y);
            __nv_bfloat16 hz = __float2bfloat16(v.z), hw = __float2bfloat16(v.w);
            __nv_bfloat162 h0(hx, hy), h1(hz, hw);
            __nv_bfloat162 l0(__float2bfloat16(v.x - __bfloat162float(hx)),
                              __float2bfloat16(v.y - __bfloat162float(hy)));
            __nv_bfloat162 l1(__float2bfloat16(v.z - __bfloat162float(hz)),
                              __float2bfloat16(v.w - __bfloat162float(hw)));
            *(uint2*)(arow + j * 8)         = make_uint2(*(uint32_t*)&h0, *(uint32_t*)&h1);
            *(uint2*)(arow + SAL + j * 8)   = make_uint2(*(uint32_t*)&l0, *(uint32_t*)&l1);
        }
    }

    float acc[2][9][4];
    #pragma unroll
    for (int a = 0; a < 2; a++)
        #pragma unroll
        for (int b = 0; b < 9; b++)
            #pragma unroll
            for (int c = 0; c < 4; c++) acc[a][b][c] = 0.f;

    uint32_t aoff = (uint32_t)((warpM * 32 + r0) * 528 + kc2 * 2);
    uint32_t boff = (uint32_t)((warpN * 72 + r0) * 80 + kc2 * 2);

    for (int sc = 0; sc < 8; sc++) {
        int buf = sc & 1;
        if (sc == 7) asm volatile("cp.async.wait_group 0;" ::: "memory");
        else         asm volatile("cp.async.wait_group 1;" ::: "memory");
        __syncthreads();
        const char* bbuf = smem + SB + buf * SBUF;
        #pragma unroll
        for (int ks = 0; ks < 2; ks++) {
            uint32_t ka = (uint32_t)(sc * 32 + ks * 16) * 2;
            const char* ap = smem + SA + aoff + ka;
            uint32_t ah[2][4], al[2][4];
            #pragma unroll
            for (int mt = 0; mt < 2; mt++) {
                const char* p = ap + mt * 8448;
                ah[mt][0] = *(const uint32_t*)(p);
                ah[mt][1] = *(const uint32_t*)(p + 4224);
                ah[mt][2] = *(const uint32_t*)(p + 16);
                ah[mt][3] = *(const uint32_t*)(p + 4240);
                const char* q = p + SAL;
                al[mt][0] = *(const uint32_t*)(q);
                al[mt][1] = *(const uint32_t*)(q + 4224);
                al[mt][2] = *(const uint32_t*)(q + 16);
                al[mt][3] = *(const uint32_t*)(q + 4240);
            }
            uint32_t kb = (uint32_t)ks * 32;
            #pragma unroll
            for (int nt = 0; nt < 9; nt++) {
                const char* bp = bbuf + boff + nt * 640 + kb;
                uint32_t bh0 = *(const uint32_t*)(bp);
                uint32_t bh1 = *(const uint32_t*)(bp + 16);
                uint32_t bl0 = *(const uint32_t*)(bp + SSP);
                uint32_t bl1 = *(const uint32_t*)(bp + SSP + 16);
                mma16816(acc[0][nt], ah[0][0], ah[0][1], ah[0][2], ah[0][3], bh0, bh1);
                mma16816(acc[1][nt], ah[1][0], ah[1][1], ah[1][2], ah[1][3], bh0, bh1);
                mma16816(acc[0][nt], al[0][0], al[0][1], al[0][2], al[0][3], bh0, bh1);
                mma16816(acc[1][nt], al[1][0], al[1][1], al[1][2], al[1][3], bh0, bh1);
                mma16816(acc[0][nt], ah[0][0], ah[0][1], ah[0][2], ah[0][3], bl0, bl1);
                mma16816(acc[1][nt], ah[1][0], ah[1][1], ah[1][2], ah[1][3], bl0, bl1);
            }
        }
        __syncthreads();
        if (sc < 6) {
            int nc = sc + 2;
            for (int i = tid; i < 2304; i += 512) {
                int sp = i / 1152, rr = i % 1152, n = rr >> 2, kv = rr & 3;
                const void* g = wbase + ((size_t)sp * NPAD + n) * 256 + nc * 32 + kv * 8;
                cpasync16(sb + SB + buf * SBUF + sp * SSP + n * 80 + kv * 16, g);
            }
            asm volatile("cp.async.commit_group;" ::: "memory");
        }
    }

    // epilogue: tail rank-3 + bias + sigmoid*softplus, stage to smem (reuse A)
    const float* wt3g = d_wt3 + layer * 3 * NB;
    float* outS = (float*)smem;   // [128][132] f32
    #pragma unroll
    for (int mt = 0; mt < 2; mt++) {
        int rbase = warpM * 32 + mt * 16 + r0;
        #pragma unroll
        for (int nt = 0; nt < 9; nt++) {
            int j = warpN * 36 + nt * 4 + tin;
            if (j >= C) continue;
            float bfv = biS[2*j], bsv = biS[2*j+1];
            float w0f = wt3g[2*j],        w0s = wt3g[2*j+1];
            float w1f = wt3g[NB + 2*j],   w1s = wt3g[NB + 2*j+1];
            float w2f = wt3g[2*NB + 2*j], w2s = wt3g[2*NB + 2*j+1];
            #pragma unroll
            for (int h = 0; h < 2; h++) {
                int r = rbase + h * 8;
                float t0 = tlS[r], t1 = tlS[128 + r], t2 = tlS[256 + r];
                float f = acc[mt][nt][2*h]   + bfv + t0*w0f + t1*w1f + t2*w2f;
                float s = acc[mt][nt][2*h+1] + bsv + t0*w0s + t1*w1s + t2*w2s;
                float sg = __fdividef(1.f, 1.f + __expf(-f));
                float sp = fmaxf(s, 0.f) + __logf(1.f + __expf(-fabsf(s)));
                outS[r * 132 + j] = sg * sp;
            }
        }
    }
    __syncthreads();

    // vector scatter: per edge 32x red.v4 (ch 0..127) + 1 scalar (ch 128)
    for (int i = tid; i < 128 * 33; i += 512) {
        int e = i / 33, g = i - e * 33;
        float* base = xn + (size_t)dstS[e] * XS;
        if (g < 32) {
            float4 v = *(const float4*)&outS[e * 132 + g * 4];
            red4(base + g * 4, v);
        } else {
            atomicAdd(base + 128, outS[e * 132 + 128]);
        }
    }
}

// ---- pooling + head ----
__global__ void zero_pool_kernel() {
    int idx = blockIdx.x * blockDim.x + threadIdx.x;
    if (idx < NUM_GRAPHS * C) d_gsum[idx] = 0.f;
    if (idx < NUM_GRAPHS)     d_gcnt[idx] = 0.f;
}
__global__ void pool_kernel(const float* __restrict__ x, const int* __restrict__ batch) {
    int idx = blockIdx.x * blockDim.x + threadIdx.x;
    if (idx >= N_NODES * C) return;
    int n = idx / C, c = idx - n * C;
    int b = batch[n];
    atomicAdd(&d_gsum[b * C + c], x[(size_t)n * XS + c]);
    if (c == 0) atomicAdd(&d_gcnt[b], 1.f);
}
__global__ void head_kernel(const float* __restrict__ Wfc, const float* __restrict__ bfc,
                            const float* __restrict__ Wout, const float* __restrict__ bout,
                            float* __restrict__ out) {
    int g = blockIdx.x, t = threadIdx.x;
    __shared__ float row[C];
    __shared__ float red[256];
    if (t < C) row[t] = d_gsum[g * C + t] / fmaxf(d_gcnt[g], 1.f);
    __syncthreads();
    for (int l = 0; l < 3; l++) {
        float y = 0.f;
        if (t < C) {
            #pragma unroll 4
            for (int k = 0; k < C; k++) y = fmaf(row[k], Wfc[(l * C + k) * C + t], y);
            y += bfc[l * C + t];
        }
        __syncthreads();
        if (t < C) row[t] = y;
        __syncthreads();
    }
    red[t] = (t < C) ? row[t] * Wout[t] : 0.f;
    __syncthreads();
    for (int s = 128; s > 0; s >>= 1) { if (t < s) red[t] += red[t + s]; __syncthreads(); }
    if (t == 0) out[g] = red[0] + bout[0];
}

extern "C" void kernel_launch(void* const* d_in, const int* in_sizes, int n_in,
                              void* d_out, int out_size) {
    const int*   atoms = (const int*)d_in[0];
    const float* pos   = (const float*)d_in[1];
    const int*   ei    = (const int*)d_in[2];
    const int*   batch = (const int*)d_in[3];
    const float* emb   = (const float*)d_in[4];
    const float* Wf    = (const float*)d_in[5];
    const float* bf    = (const float*)d_in[6];
    const float* Ws    = (const float*)d_in[7];
    const float* bs    = (const float*)d_in[8];
    const float* Wfc   = (const float*)d_in[9];
    const float* bfc   = (const float*)d_in[10];
    const float* Wout  = (const float*)d_in[11];
    const float* bout  = (const float*)d_in[12];
    float* out = (float*)d_out;

    cudaFuncSetAttribute(edge_mma_kernel,
                         cudaFuncAttributeMaxDynamicSharedMemorySize, SMEM_TOTAL);

    float *xa, *xb;
    cudaGetSymbolAddress((void**)&xa, d_xa);
    cudaGetSymbolAddress((void**)&xb, d_xb);

    pack_wb_kernel<<<(NLAYERS*2*NPAD*256 + 255)/256, 256>>>(Wf, Ws);
    pack_tail_kernel<<<(NLAYERS*3*NB + 255)/256, 256>>>(Wf, Ws);
    pack_bias_kernel<<<(NLAYERS*NB + 255)/256, 256>>>(bf, bs);
    init_x_kernel<<<(N_NODES*XS + 255)/256, 256>>>(atoms, pos, emb);
    ea_kernel<<<(N_EDGES + 255)/256, 256>>>(ei, pos);

    const int n4 = N_NODES * XS / 4;
    float* cur = xa;
    float* nxt = xb;
    for (int l = 0; l < NLAYERS; l++) {
        copy4_kernel<<<(n4 + 255)/256, 256>>>((const float4*)cur, (float4*)nxt, n4);
        edge_mma_kernel<<<N_EDGES / 128, 512, SMEM_TOTAL>>>(cur, nxt, ei, l);
        float* tmp = cur; cur = nxt; nxt = tmp;
    }

    zero_pool_kernel<<<(NUM_GRAPHS*C + 255)/256, 256>>>();
    pool_kernel<<<(N_NODES*C + 255)/256, 256>>>(cur, batch);
    head_kernel<<<NUM_GRAPHS, 256>>>(Wfc, bfc, Wout, bout, out);
}

// round 5
// speedup vs baseline: 14.3675x; 4.4366x over previous
#include <cuda_runtime.h>
#include <cuda_bf16.h>
#include <cstdint>
#include <math.h>

#define N_NODES   50000
#define NROWS     50048     // padded to 391*128
#define N_EDGES   800000
#define NUM_GRAPHS 256
#define C         129
#define ZDIM      259
#define NLAYERS   5
#define XS        160       // padded x row stride (floats), K of node GEMM
#define PLN       132       // plane width (channels padded)
#define NCOL      264       // 2 planes per half
#define NPG       288       // padded GEMM N per half

// GEMM smem offsets
#define GSA    0            // A hi: 128 x 336B
#define GSAL   43008        // A lo
#define GSB    86016        // B: 2 bufs x (2 splits x 288 x 80B)
#define GSSP   23040
#define GSBUF  46080
#define GSBI   178176       // bias 288 f32
#define GSMEM  179328

__device__ __align__(16) __nv_bfloat16 d_wbN[NLAYERS*2*2*5*NPG*32];
__device__ float d_bph[NLAYERS*2*NPG];
__device__ float d_w3[NLAYERS*NCOL];
__device__ __align__(16) float d_xa[NROWS*XS];
__device__ __align__(16) float d_xb[NROWS*XS];
__device__ __align__(16) float d_P[(size_t)NROWS*528];
__device__ float d_ea[N_EDGES];
__device__ float d_gsum[NUM_GRAPHS*C];
__device__ float d_gcnt[NUM_GRAPHS];

__device__ __forceinline__ uint32_t smem_u32(const void* p){
    uint32_t a;
    asm("{ .reg .u64 t; cvta.to.shared.u64 t, %1; cvt.u32.u64 %0, t; }" : "=r"(a) : "l"(p));
    return a;
}
__device__ __forceinline__ void mma16816(float* d, uint32_t a0, uint32_t a1,
                                         uint32_t a2, uint32_t a3,
                                         uint32_t b0, uint32_t b1){
    asm volatile(
        "mma.sync.aligned.m16n8k16.row.col.f32.bf16.bf16.f32 "
        "{%0,%1,%2,%3}, {%4,%5,%6,%7}, {%8,%9}, {%0,%1,%2,%3};"
        : "+f"(d[0]), "+f"(d[1]), "+f"(d[2]), "+f"(d[3])
        : "r"(a0), "r"(a1), "r"(a2), "r"(a3), "r"(b0), "r"(b1));
}
__device__ __forceinline__ void cpasync16(uint32_t s, const void* g){
    asm volatile("cp.async.cg.shared.global [%0], [%1], 16;" :: "r"(s), "l"(g));
}
__device__ __forceinline__ void red4(float* p, float4 v){
    asm volatile("red.global.add.v4.f32 [%0], {%1,%2,%3,%4};"
                 :: "l"(p), "f"(v.x), "f"(v.y), "f"(v.z), "f"(v.w) : "memory");
}

// ---- prepack W for node GEMM: [l][half][split][kc 5][n 288][k 32] bf16 ----
__global__ void pack_wbN_kernel(const float* __restrict__ Wf, const float* __restrict__ Ws){
    int idx = blockIdx.x * blockDim.x + threadIdx.x;
    if (idx >= NLAYERS*2*2*5*NPG*32) return;
    int k  = idx & 31;
    int n  = (idx >> 5) % NPG;
    int kc = (idx / (32*NPG)) % 5;
    int sp = (idx / (32*NPG*5)) & 1;
    int hf = (idx / (32*NPG*5*2)) & 1;
    int l  = idx / (32*NPG*5*2*2);
    int kg = kc*32 + k;
    float w = 0.f;
    if (n < NCOL && kg < C){
        int plane = n / PLN, j = n % PLN;
        if (j < C){
            int zi = hf ? (C + kg) : kg;
            const float* W = plane ? Ws : Wf;
            w = W[(l*ZDIM + zi)*C + j];
        }
    }
    __nv_bfloat16 hi = __float2bfloat16(w);
    d_wbN[idx] = sp ? __float2bfloat16(w - __bfloat162float(hi)) : hi;
}
__global__ void pack_bph_kernel(const float* __restrict__ bf, const float* __restrict__ bs){
    int idx = blockIdx.x * blockDim.x + threadIdx.x;
    if (idx >= NLAYERS*2*NPG) return;
    int n = idx % NPG, hf = (idx / NPG) & 1, l = idx / (2*NPG);
    float v = 0.f;
    if (hf == 0 && n < NCOL){
        int plane = n / PLN, j = n % PLN;
        if (j < C) v = plane ? bs[l*C + j] : bf[l*C + j];
    }
    d_bph[idx] = v;
}
__global__ void pack_w3_kernel(const float* __restrict__ Wf, const float* __restrict__ Ws){
    int idx = blockIdx.x * blockDim.x + threadIdx.x;
    if (idx >= NLAYERS*NCOL) return;
    int n = idx % NCOL, l = idx / NCOL;
    int plane = n / PLN, j = n % PLN;
    float v = 0.f;
    if (j < C){ const float* W = plane ? Ws : Wf; v = W[(l*ZDIM + 258)*C + j]; }
    d_w3[idx] = v;
}
__global__ void init_x_kernel(const int* __restrict__ atoms, const float* __restrict__ pos,
                              const float* __restrict__ emb){
    int idx = blockIdx.x * blockDim.x + threadIdx.x;
    if (idx >= NROWS*XS) return;
    int n = idx / XS, c = idx - n*XS;
    float v = 0.f;
    if (n < N_NODES){
        if (c < 128) v = emb[atoms[n]*128 + c];
        else if (c == 128) v = pos[n*3 + 2];
    }
    d_xa[idx] = v;
}
__global__ void ea_kernel(const int* __restrict__ ei, const float* __restrict__ pos){
    int e = blockIdx.x * blockDim.x + threadIdx.x;
    if (e >= N_EDGES) return;
    int s = ei[e], d = ei[N_EDGES + e];
    float dx = pos[s*3]-pos[d*3], dy = pos[s*3+1]-pos[d*3+1], dz = pos[s*3+2]-pos[d*3+2];
    d_ea[e] = sqrtf(dx*dx + dy*dy + dz*dz);
}
__global__ void copy4_kernel(const float4* __restrict__ a, float4* __restrict__ b, int n4){
    int i = blockIdx.x * blockDim.x + threadIdx.x;
    if (i < n4) b[i] = a[i];
}

// ---- node GEMM: P[half] = Xsplit @ Wcat(bf16 3-term), bias folded (half0) ----
__global__ __launch_bounds__(512, 1)
void node_gemm_kernel(const float* __restrict__ xc, int layer){
    extern __shared__ __align__(16) char smem[];
    uint32_t sb = smem_u32(smem);
    int tid = threadIdx.x, lane = tid & 31, wid = tid >> 5;
    int r0 = lane >> 2, tin = lane & 3;
    int warpM = wid & 3, warpN = wid >> 2;
    int m0 = blockIdx.x * 128;
    int hf = blockIdx.y;

    const __nv_bfloat16* wbase = d_wbN + (size_t)((layer*2 + hf)*2) * 5*NPG*32;

    #pragma unroll
    for (int pc = 0; pc < 2; pc++){
        for (int i = tid; i < 2304; i += 512){
            int sp = i / 1152, rr = i % 1152, n = rr >> 2, kv = rr & 3;
            const void* g = wbase + ((size_t)sp*5 + pc)*NPG*32 + n*32 + kv*8;
            cpasync16(sb + GSB + pc*GSBUF + sp*GSSP + n*80 + kv*16, g);
        }
        asm volatile("cp.async.commit_group;" ::: "memory");
    }
    float* biS = (float*)(smem + GSBI);
    for (int i = tid; i < NPG; i += 512) biS[i] = d_bph[(layer*2 + hf)*NPG + i];

    // A stage: hi/lo bf16, row = tid>>2 (0..127), quarter q = tid&3 (40 floats)
    {
        int row = tid >> 2, q = tid & 3;
        const float4* xr = (const float4*)(xc + (size_t)(m0 + row)*XS) + q*10;
        char* arow = smem + GSA + row*336 + q*80;
        #pragma unroll
        for (int j = 0; j < 10; j++){
            float4 v = xr[j];
            __nv_bfloat16 hx = __float2bfloat16(v.x), hy = __float2bfloat16(v.y);
            __nv_bfloat16 hz = __float2bfloat16(v.z), hw = __float2bfloat16(v.w);
            __nv_bfloat162 h0(hx, hy), h1(hz, hw);
            __nv_bfloat162 l0(__float2bfloat16(v.x - __bfloat162float(hx)),
                              __float2bfloat16(v.y - __bfloat162float(hy)));
            __nv_bfloat162 l1(__float2bfloat16(v.z - __bfloat162float(hz)),
                              __float2bfloat16(v.w - __bfloat162float(hw)));
            *(uint2*)(arow + j*8)        = make_uint2(*(uint32_t*)&h0, *(uint32_t*)&h1);
            *(uint2*)(arow + GSAL + j*8) = make_uint2(*(uint32_t*)&l0, *(uint32_t*)&l1);
        }
    }

    float acc[2][9][4];
    #pragma unroll
    for (int a = 0; a < 2; a++)
        #pragma unroll
        for (int b = 0; b < 9; b++)
            #pragma unroll
            for (int c = 0; c < 4; c++) acc[a][b][c] = 0.f;

    uint32_t aoff = (uint32_t)((warpM*32 + r0)*336 + tin*4);
    uint32_t boff = (uint32_t)((warpN*72 + r0)*80 + tin*4);

    for (int sc = 0; sc < 5; sc++){
        int buf = sc & 1;
        if (sc == 4) asm volatile("cp.async.wait_group 0;" ::: "memory");
        else         asm volatile("cp.async.wait_group 1;" ::: "memory");
        __syncthreads();
        const char* bbuf = smem + GSB + buf*GSBUF;
        #pragma unroll
        for (int ks = 0; ks < 2; ks++){
            uint32_t ka = (uint32_t)(sc*32 + ks*16)*2;
            const char* ap = smem + GSA + aoff + ka;
            uint32_t ah[2][4], al[2][4];
            #pragma unroll
            for (int mt = 0; mt < 2; mt++){
                const char* p = ap + mt*5376;
                ah[mt][0] = *(const uint32_t*)(p);
                ah[mt][1] = *(const uint32_t*)(p + 2688);
                ah[mt][2] = *(const uint32_t*)(p + 16);
                ah[mt][3] = *(const uint32_t*)(p + 2704);
                const char* q = p + GSAL;
                al[mt][0] = *(const uint32_t*)(q);
                al[mt][1] = *(const uint32_t*)(q + 2688);
                al[mt][2] = *(const uint32_t*)(q + 16);
                al[mt][3] = *(const uint32_t*)(q + 2704);
            }
            uint32_t kb = (uint32_t)ks*32;
            #pragma unroll
            for (int nt = 0; nt < 9; nt++){
                const char* bp = bbuf + boff + nt*640 + kb;
                uint32_t bh0 = *(const uint32_t*)(bp);
                uint32_t bh1 = *(const uint32_t*)(bp + 16);
                uint32_t bl0 = *(const uint32_t*)(bp + GSSP);
                uint32_t bl1 = *(const uint32_t*)(bp + GSSP + 16);
                mma16816(acc[0][nt], ah[0][0], ah[0][1], ah[0][2], ah[0][3], bh0, bh1);
                mma16816(acc[1][nt], ah[1][0], ah[1][1], ah[1][2], ah[1][3], bh0, bh1);
                mma16816(acc[0][nt], al[0][0], al[0][1], al[0][2], al[0][3], bh0, bh1);
                mma16816(acc[1][nt], al[1][0], al[1][1], al[1][2], al[1][3], bh0, bh1);
                mma16816(acc[0][nt], ah[0][0], ah[0][1], ah[0][2], ah[0][3], bl0, bl1);
                mma16816(acc[1][nt], ah[1][0], ah[1][1], ah[1][2], ah[1][3], bl0, bl1);
            }
        }
        __syncthreads();
        if (sc < 3){
            int nc = sc + 2;
            for (int i = tid; i < 2304; i += 512){
                int sp = i / 1152, rr = i % 1152, n = rr >> 2, kv = rr & 3;
                const void* g = wbase + ((size_t)sp*5 + nc)*NPG*32 + n*32 + kv*8;
                cpasync16(sb + GSB + buf*GSBUF + sp*GSSP + n*80 + kv*16, g);
            }
            asm volatile("cp.async.commit_group;" ::: "memory");
        }
    }

    // store P (+bias)
    size_t colbase = (size_t)hf * NCOL;
    #pragma unroll
    for (int mt = 0; mt < 2; mt++){
        #pragma unroll
        for (int nt = 0; nt < 9; nt++){
            int col = warpN*72 + nt*8 + tin*2;
            if (col >= NCOL) continue;
            float b0 = biS[col], b1 = biS[col + 1];
            #pragma unroll
            for (int h = 0; h < 2; h++){
                int row = m0 + warpM*32 + mt*16 + r0 + h*8;
                float2 v = make_float2(acc[mt][nt][2*h] + b0, acc[mt][nt][2*h+1] + b1);
                *(float2*)(d_P + (size_t)row*528 + colbase + col) = v;
            }
        }
    }
}

// ---- edge apply: m = sig(P1f[dst]+P2f[src]+e*w3f) * sp(P1s+P2s+e*w3s), scatter ----
__global__ __launch_bounds__(256)
void edge_apply_kernel(float* __restrict__ xn, const int* __restrict__ ei, int layer){
    int lane = threadIdx.x & 31, warp = threadIdx.x >> 5;
    int e = blockIdx.x * 8 + warp;
    int src = ei[e], dst = ei[N_EDGES + e];
    float eav = d_ea[e];
    const float* p1 = d_P + (size_t)dst * 528;
    const float* p2 = d_P + (size_t)src * 528 + NCOL;
    const float* w3 = d_w3 + layer * NCOL;

    float4 f1 = *(const float4*)(p1 + lane*4);
    float4 s1 = *(const float4*)(p1 + PLN + lane*4);
    float4 f2 = *(const float4*)(p2 + lane*4);
    float4 s2 = *(const float4*)(p2 + PLN + lane*4);
    float4 wf = *(const float4*)(w3 + lane*4);
    float4 ws = *(const float4*)(w3 + PLN + lane*4);

    float4 m;
    {
        float f, s;
        f = f1.x + f2.x + eav*wf.x; s = s1.x + s2.x + eav*ws.x;
        m.x = __fdividef(1.f, 1.f + __expf(-f)) * (fmaxf(s,0.f) + __logf(1.f + __expf(-fabsf(s))));
        f = f1.y + f2.y + eav*wf.y; s = s1.y + s2.y + eav*ws.y;
        m.y = __fdividef(1.f, 1.f + __expf(-f)) * (fmaxf(s,0.f) + __logf(1.f + __expf(-fabsf(s))));
        f = f1.z + f2.z + eav*wf.z; s = s1.z + s2.z + eav*ws.z;
        m.z = __fdividef(1.f, 1.f + __expf(-f)) * (fmaxf(s,0.f) + __logf(1.f + __expf(-fabsf(s))));
        f = f1.w + f2.w + eav*wf.w; s = s1.w + s2.w + eav*ws.w;
        m.w = __fdividef(1.f, 1.f + __expf(-f)) * (fmaxf(s,0.f) + __logf(1.f + __expf(-fabsf(s))));
    }
    red4(xn + (size_t)dst*XS + lane*4, m);

    if (lane == 0){
        float f = p1[128] + p2[128] + eav*w3[128];
        float s = p1[PLN + 128] + p2[PLN + 128] + eav*w3[PLN + 128];
        float mv = __fdividef(1.f, 1.f + __expf(-f)) * (fmaxf(s,0.f) + __logf(1.f + __expf(-fabsf(s))));
        atomicAdd(xn + (size_t)dst*XS + 128, mv);
    }
}

// ---- pooling + head ----
__global__ void zero_pool_kernel(){
    int idx = blockIdx.x * blockDim.x + threadIdx.x;
    if (idx < NUM_GRAPHS*C) d_gsum[idx] = 0.f;
    if (idx < NUM_GRAPHS)   d_gcnt[idx] = 0.f;
}
__global__ void pool_kernel(const float* __restrict__ x, const int* __restrict__ batch){
    int idx = blockIdx.x * blockDim.x + threadIdx.x;
    if (idx >= N_NODES*C) return;
    int n = idx / C, c = idx - n*C;
    int b = batch[n];
    atomicAdd(&d_gsum[b*C + c], x[(size_t)n*XS + c]);
    if (c == 0) atomicAdd(&d_gcnt[b], 1.f);
}
__global__ void head_kernel(const float* __restrict__ Wfc, const float* __restrict__ bfc,
                            const float* __restrict__ Wout, const float* __restrict__ bout,
                            float* __restrict__ out){
    int g = blockIdx.x, t = threadIdx.x;
    __shared__ float row[C];
    __shared__ float red[256];
    if (t < C) row[t] = d_gsum[g*C + t] / fmaxf(d_gcnt[g], 1.f);
    __syncthreads();
    for (int l = 0; l < 3; l++){
        float y = 0.f;
        if (t < C){
            #pragma unroll 4
            for (int k = 0; k < C; k++) y = fmaf(row[k], Wfc[(l*C + k)*C + t], y);
            y += bfc[l*C + t];
        }
        __syncthreads();
        if (t < C) row[t] = y;
        __syncthreads();
    }
    red[t] = (t < C) ? row[t]*Wout[t] : 0.f;
    __syncthreads();
    for (int s = 128; s > 0; s >>= 1){ if (t < s) red[t] += red[t + s]; __syncthreads(); }
    if (t == 0) out[g] = red[0] + bout[0];
}

extern "C" void kernel_launch(void* const* d_in, const int* in_sizes, int n_in,
                              void* d_out, int out_size){
    const int*   atoms = (const int*)d_in[0];
    const float* pos   = (const float*)d_in[1];
    const int*   ei    = (const int*)d_in[2];
    const int*   batch = (const int*)d_in[3];
    const float* emb   = (const float*)d_in[4];
    const float* Wf    = (const float*)d_in[5];
    const float* bf    = (const float*)d_in[6];
    const float* Ws    = (const float*)d_in[7];
    const float* bs    = (const float*)d_in[8];
    const float* Wfc   = (const float*)d_in[9];
    const float* bfc   = (const float*)d_in[10];
    const float* Wout  = (const float*)d_in[11];
    const float* bout  = (const float*)d_in[12];
    float* out = (float*)d_out;

    cudaFuncSetAttribute(node_gemm_kernel,
                         cudaFuncAttributeMaxDynamicSharedMemorySize, GSMEM);

    float *xa, *xb;
    cudaGetSymbolAddress((void**)&xa, d_xa);
    cudaGetSymbolAddress((void**)&xb, d_xb);

    pack_wbN_kernel<<<(NLAYERS*2*2*5*NPG*32 + 255)/256, 256>>>(Wf, Ws);
    pack_bph_kernel<<<(NLAYERS*2*NPG + 255)/256, 256>>>(bf, bs);
    pack_w3_kernel<<<(NLAYERS*NCOL + 255)/256, 256>>>(Wf, Ws);
    init_x_kernel<<<(NROWS*XS + 255)/256, 256>>>(atoms, pos, emb);
    ea_kernel<<<(N_EDGES + 255)/256, 256>>>(ei, pos);

    const int n4 = NROWS*XS/4;
    float* cur = xa;
    float* nxt = xb;
    for (int l = 0; l < NLAYERS; l++){
        node_gemm_kernel<<<dim3(NROWS/128, 2), 512, GSMEM>>>(cur, l);
        copy4_kernel<<<(n4 + 255)/256, 256>>>((const float4*)cur, (float4*)nxt, n4);
        edge_apply_kernel<<<N_EDGES/8, 256>>>(nxt, ei, l);
        float* tmp = cur; cur = nxt; nxt = tmp;
    }

    zero_pool_kernel<<<(NUM_GRAPHS*C + 255)/256, 256>>>();
    pool_kernel<<<(N_NODES*C + 255)/256, 256>>>(cur, batch);
    head_kernel<<<NUM_GRAPHS, 256>>>(Wfc, bfc, Wout, bout, out);
}

// round 6
// speedup vs baseline: 17.4413x; 1.2139x over previous
#include <cuda_runtime.h>
#include <cuda_bf16.h>
#include <cstdint>
#include <math.h>

#define N_NODES   50000
#define NROWS     50048
#define N_EDGES   800000
#define NUM_GRAPHS 256
#define C         129
#define ZDIM      259
#define NLAYERS   5
#define XS        160
#define PLN       132
#define NCOL      264
#define NPG       288

// GEMM smem offsets
#define GSA    0
#define GSAL   43008
#define GSB    86016
#define GSSP   23040
#define GSBUF  46080
#define GSBI   178176
#define GSMEM  179328

__device__ __align__(16) __nv_bfloat16 d_wbN[NLAYERS*2*2*5*NPG*32];
__device__ float d_bph[NLAYERS*2*NPG];
__device__ float d_w3[NLAYERS*NCOL];
__device__ __align__(16) float d_xa[NROWS*XS];
__device__ __align__(16) float d_xb[NROWS*XS];
__device__ __align__(16) float d_P[(size_t)NROWS*528];
__device__ int   d_cnt[N_NODES];
__device__ int   d_rowptr[N_NODES + 1];
__device__ int   d_pos[N_NODES];
__device__ int   d_srcS[N_EDGES];
__device__ float d_eaS[N_EDGES];
__device__ float d_gsum[NUM_GRAPHS*PLN];
__device__ float d_gcnt[NUM_GRAPHS];

__device__ __forceinline__ uint32_t smem_u32(const void* p){
    uint32_t a;
    asm("{ .reg .u64 t; cvta.to.shared.u64 t, %1; cvt.u32.u64 %0, t; }" : "=r"(a) : "l"(p));
    return a;
}
__device__ __forceinline__ void mma16816(float* d, uint32_t a0, uint32_t a1,
                                         uint32_t a2, uint32_t a3,
                                         uint32_t b0, uint32_t b1){
    asm volatile(
        "mma.sync.aligned.m16n8k16.row.col.f32.bf16.bf16.f32 "
        "{%0,%1,%2,%3}, {%4,%5,%6,%7}, {%8,%9}, {%0,%1,%2,%3};"
        : "+f"(d[0]), "+f"(d[1]), "+f"(d[2]), "+f"(d[3])
        : "r"(a0), "r"(a1), "r"(a2), "r"(a3), "r"(b0), "r"(b1));
}
__device__ __forceinline__ void cpasync16(uint32_t s, const void* g){
    asm volatile("cp.async.cg.shared.global [%0], [%1], 16;" :: "r"(s), "l"(g));
}
__device__ __forceinline__ void red4(float* p, float4 v){
    asm volatile("red.global.add.v4.f32 [%0], {%1,%2,%3,%4};"
                 :: "l"(p), "f"(v.x), "f"(v.y), "f"(v.z), "f"(v.w) : "memory");
}
__device__ __forceinline__ float gact(float f, float s){
    float sg = __fdividef(1.f, 1.f + __expf(-f));
    float sp = fmaxf(s, 0.f) + __logf(1.f + __expf(-fabsf(s)));
    return sg * sp;
}

// ---- prepack ----
__global__ void pack_wbN_kernel(const float* __restrict__ Wf, const float* __restrict__ Ws){
    int idx = blockIdx.x * blockDim.x + threadIdx.x;
    if (idx >= NLAYERS*2*2*5*NPG*32) return;
    int k  = idx & 31;
    int n  = (idx >> 5) % NPG;
    int kc = (idx / (32*NPG)) % 5;
    int sp = (idx / (32*NPG*5)) & 1;
    int hf = (idx / (32*NPG*5*2)) & 1;
    int l  = idx / (32*NPG*5*2*2);
    int kg = kc*32 + k;
    float w = 0.f;
    if (n < NCOL && kg < C){
        int plane = n / PLN, j = n % PLN;
        if (j < C){
            int zi = hf ? (C + kg) : kg;
            const float* W = plane ? Ws : Wf;
            w = W[(l*ZDIM + zi)*C + j];
        }
    }
    __nv_bfloat16 hi = __float2bfloat16(w);
    d_wbN[idx] = sp ? __float2bfloat16(w - __bfloat162float(hi)) : hi;
}
__global__ void pack_bph_kernel(const float* __restrict__ bf, const float* __restrict__ bs){
    int idx = blockIdx.x * blockDim.x + threadIdx.x;
    if (idx >= NLAYERS*2*NPG) return;
    int n = idx % NPG, hf = (idx / NPG) & 1, l = idx / (2*NPG);
    float v = 0.f;
    if (hf == 0 && n < NCOL){
        int plane = n / PLN, j = n % PLN;
        if (j < C) v = plane ? bs[l*C + j] : bf[l*C + j];
    }
    d_bph[idx] = v;
}
__global__ void pack_w3_kernel(const float* __restrict__ Wf, const float* __restrict__ Ws){
    int idx = blockIdx.x * blockDim.x + threadIdx.x;
    if (idx >= NLAYERS*NCOL) return;
    int n = idx % NCOL, l = idx / NCOL;
    int plane = n / PLN, j = n % PLN;
    float v = 0.f;
    if (j < C){ const float* W = plane ? Ws : Wf; v = W[(l*ZDIM + 258)*C + j]; }
    d_w3[idx] = v;
}
__global__ void init_x_kernel(const int* __restrict__ atoms, const float* __restrict__ pos,
                              const float* __restrict__ emb){
    int idx = blockIdx.x * blockDim.x + threadIdx.x;
    if (idx >= NROWS*XS) return;
    int n = idx / XS, c = idx - n*XS;
    float v = 0.f;
    if (n < N_NODES){
        if (c < 128) v = emb[atoms[n]*128 + c];
        else if (c == 128) v = pos[n*3 + 2];
    }
    d_xa[idx] = v;
}

// ---- CSR build ----
__global__ void zero_cnt_kernel(){
    int i = blockIdx.x * blockDim.x + threadIdx.x;
    if (i < N_NODES) d_cnt[i] = 0;
}
__global__ void hist_kernel(const int* __restrict__ ei){
    int e = blockIdx.x * blockDim.x + threadIdx.x;
    if (e < N_EDGES) atomicAdd(&d_cnt[ei[N_EDGES + e]], 1);
}
__global__ void scan_kernel(){
    __shared__ int wsum[32];
    __shared__ int carry;
    int tid = threadIdx.x, lane = tid & 31, wid = tid >> 5;
    if (tid == 0) carry = 0;
    __syncthreads();
    for (int base = 0; base < N_NODES; base += 1024){
        int i = base + tid;
        int v = (i < N_NODES) ? d_cnt[i] : 0;
        int x = v;
        #pragma unroll
        for (int d = 1; d < 32; d <<= 1){
            int y = __shfl_up_sync(0xffffffffu, x, d);
            if (lane >= d) x += y;
        }
        if (lane == 31) wsum[wid] = x;
        __syncthreads();
        if (wid == 0){
            int s = wsum[lane];
            #pragma unroll
            for (int d = 1; d < 32; d <<= 1){
                int y = __shfl_up_sync(0xffffffffu, s, d);
                if (lane >= d) s += y;
            }
            wsum[lane] = s;
        }
        __syncthreads();
        int excl = x - v + (wid ? wsum[wid-1] : 0) + carry;
        if (i < N_NODES){ d_rowptr[i] = excl; d_pos[i] = excl; }
        __syncthreads();
        if (tid == 0) carry += wsum[31];
        __syncthreads();
    }
    if (threadIdx.x == 0) d_rowptr[N_NODES] = carry;
}
__global__ void scatter_kernel(const int* __restrict__ ei, const float* __restrict__ pos){
    int e = blockIdx.x * blockDim.x + threadIdx.x;
    if (e >= N_EDGES) return;
    int s = ei[e], d = ei[N_EDGES + e];
    float dx = pos[s*3]-pos[d*3], dy = pos[s*3+1]-pos[d*3+1], dz = pos[s*3+2]-pos[d*3+2];
    float eav = sqrtf(dx*dx + dy*dy + dz*dz);
    int p = atomicAdd(&d_pos[d], 1);
    d_srcS[p] = s;
    d_eaS[p] = eav;
}

// ---- node GEMM (unchanged structure) ----
__global__ __launch_bounds__(512, 1)
void node_gemm_kernel(const float* __restrict__ xc, int layer){
    extern __shared__ __align__(16) char smem[];
    uint32_t sb = smem_u32(smem);
    int tid = threadIdx.x, lane = tid & 31, wid = tid >> 5;
    int r0 = lane >> 2, tin = lane & 3;
    int warpM = wid & 3, warpN = wid >> 2;
    int m0 = blockIdx.x * 128;
    int hf = blockIdx.y;

    const __nv_bfloat16* wbase = d_wbN + (size_t)((layer*2 + hf)*2) * 5*NPG*32;

    #pragma unroll
    for (int pc = 0; pc < 2; pc++){
        for (int i = tid; i < 2304; i += 512){
            int sp = i / 1152, rr = i % 1152, n = rr >> 2, kv = rr & 3;
            const void* g = wbase + ((size_t)sp*5 + pc)*NPG*32 + n*32 + kv*8;
            cpasync16(sb + GSB + pc*GSBUF + sp*GSSP + n*80 + kv*16, g);
        }
        asm volatile("cp.async.commit_group;" ::: "memory");
    }
    float* biS = (float*)(smem + GSBI);
    for (int i = tid; i < NPG; i += 512) biS[i] = d_bph[(layer*2 + hf)*NPG + i];

    {
        int row = tid >> 2, q = tid & 3;
        const float4* xr = (const float4*)(xc + (size_t)(m0 + row)*XS) + q*10;
        char* arow = smem + GSA + row*336 + q*80;
        #pragma unroll
        for (int j = 0; j < 10; j++){
            float4 v = xr[j];
            __nv_bfloat16 hx = __float2bfloat16(v.x), hy = __float2bfloat16(v.y);
            __nv_bfloat16 hz = __float2bfloat16(v.z), hw = __float2bfloat16(v.w);
            __nv_bfloat162 h0(hx, hy), h1(hz, hw);
            __nv_bfloat162 l0(__float2bfloat16(v.x - __bfloat162float(hx)),
                              __float2bfloat16(v.y - __bfloat162float(hy)));
            __nv_bfloat162 l1(__float2bfloat16(v.z - __bfloat162float(hz)),
                              __float2bfloat16(v.w - __bfloat162float(hw)));
            *(uint2*)(arow + j*8)        = make_uint2(*(uint32_t*)&h0, *(uint32_t*)&h1);
            *(uint2*)(arow + GSAL + j*8) = make_uint2(*(uint32_t*)&l0, *(uint32_t*)&l1);
        }
    }

    float acc[2][9][4];
    #pragma unroll
    for (int a = 0; a < 2; a++)
        #pragma unroll
        for (int b = 0; b < 9; b++)
            #pragma unroll
            for (int c = 0; c < 4; c++) acc[a][b][c] = 0.f;

    uint32_t aoff = (uint32_t)((warpM*32 + r0)*336 + tin*4);
    uint32_t boff = (uint32_t)((warpN*72 + r0)*80 + tin*4);

    for (int sc = 0; sc < 5; sc++){
        int buf = sc & 1;
        if (sc == 4) asm volatile("cp.async.wait_group 0;" ::: "memory");
        else         asm volatile("cp.async.wait_group 1;" ::: "memory");
        __syncthreads();
        const char* bbuf = smem + GSB + buf*GSBUF;
        #pragma unroll
        for (int ks = 0; ks < 2; ks++){
            uint32_t ka = (uint32_t)(sc*32 + ks*16)*2;
            const char* ap = smem + GSA + aoff + ka;
            uint32_t ah[2][4], al[2][4];
            #pragma unroll
            for (int mt = 0; mt < 2; mt++){
                const char* p = ap + mt*5376;
                ah[mt][0] = *(const uint32_t*)(p);
                ah[mt][1] = *(const uint32_t*)(p + 2688);
                ah[mt][2] = *(const uint32_t*)(p + 16);
                ah[mt][3] = *(const uint32_t*)(p + 2704);
                const char* q = p + GSAL;
                al[mt][0] = *(const uint32_t*)(q);
                al[mt][1] = *(const uint32_t*)(q + 2688);
                al[mt][2] = *(const uint32_t*)(q + 16);
                al[mt][3] = *(const uint32_t*)(q + 2704);
            }
            uint32_t kb = (uint32_t)ks*32;
            #pragma unroll
            for (int nt = 0; nt < 9; nt++){
                const char* bp = bbuf + boff + nt*640 + kb;
                uint32_t bh0 = *(const uint32_t*)(bp);
                uint32_t bh1 = *(const uint32_t*)(bp + 16);
                uint32_t bl0 = *(const uint32_t*)(bp + GSSP);
                uint32_t bl1 = *(const uint32_t*)(bp + GSSP + 16);
                mma16816(acc[0][nt], ah[0][0], ah[0][1], ah[0][2], ah[0][3], bh0, bh1);
                mma16816(acc[1][nt], ah[1][0], ah[1][1], ah[1][2], ah[1][3], bh0, bh1);
                mma16816(acc[0][nt], al[0][0], al[0][1], al[0][2], al[0][3], bh0, bh1);
                mma16816(acc[1][nt], al[1][0], al[1][1], al[1][2], al[1][3], bh0, bh1);
                mma16816(acc[0][nt], ah[0][0], ah[0][1], ah[0][2], ah[0][3], bl0, bl1);
                mma16816(acc[1][nt], ah[1][0], ah[1][1], ah[1][2], ah[1][3], bl0, bl1);
            }
        }
        __syncthreads();
        if (sc < 3){
            int nc = sc + 2;
            for (int i = tid; i < 2304; i += 512){
                int sp = i / 1152, rr = i % 1152, n = rr >> 2, kv = rr & 3;
                const void* g = wbase + ((size_t)sp*5 + nc)*NPG*32 + n*32 + kv*8;
                cpasync16(sb + GSB + buf*GSBUF + sp*GSSP + n*80 + kv*16, g);
            }
            asm volatile("cp.async.commit_group;" ::: "memory");
        }
    }

    size_t colbase = (size_t)hf * NCOL;
    #pragma unroll
    for (int mt = 0; mt < 2; mt++){
        #pragma unroll
        for (int nt = 0; nt < 9; nt++){
            int col = warpN*72 + nt*8 + tin*2;
            if (col >= NCOL) continue;
            float b0 = biS[col], b1 = biS[col + 1];
            #pragma unroll
            for (int h = 0; h < 2; h++){
                int row = m0 + warpM*32 + mt*16 + r0 + h*8;
                float2 v = make_float2(acc[mt][nt][2*h] + b0, acc[mt][nt][2*h+1] + b1);
                *(float2*)(d_P + (size_t)row*528 + colbase + col) = v;
            }
        }
    }
}

// ---- edge phase: warp-per-node CSR, fused residual copy, no atomics ----
__global__ __launch_bounds__(256)
void edge_csr_kernel(const float* __restrict__ xc, float* __restrict__ xn, int layer){
    int lane = threadIdx.x & 31, warp = threadIdx.x >> 5;
    int n = blockIdx.x * 8 + warp;   // grid covers exactly N_NODES
    const float* w3 = d_w3 + layer * NCOL;
    float4 wf = *(const float4*)(w3 + lane*4);
    float4 ws = *(const float4*)(w3 + PLN + lane*4);
    const float* p1 = d_P + (size_t)n * 528;
    float4 f1 = *(const float4*)(p1 + lane*4);
    float4 s1 = *(const float4*)(p1 + PLN + lane*4);
    float f1t = 0.f, s1t = 0.f, wft = 0.f, wst = 0.f;
    if (lane == 0){
        f1t = p1[128]; s1t = p1[PLN + 128];
        wft = w3[128]; wst = w3[PLN + 128];
    }
    int beg = d_rowptr[n], end = d_rowptr[n + 1];
    float4 acc = make_float4(0.f, 0.f, 0.f, 0.f);
    float acct = 0.f;
    for (int i = beg; i < end; i++){
        int src = d_srcS[i];
        float eav = d_eaS[i];
        const float* p2 = d_P + (size_t)src * 528 + NCOL;
        float4 f2 = *(const float4*)(p2 + lane*4);
        float4 s2 = *(const float4*)(p2 + PLN + lane*4);
        acc.x += gact(f1.x + f2.x + eav*wf.x, s1.x + s2.x + eav*ws.x);
        acc.y += gact(f1.y + f2.y + eav*wf.y, s1.y + s2.y + eav*ws.y);
        acc.z += gact(f1.z + f2.z + eav*wf.z, s1.z + s2.z + eav*ws.z);
        acc.w += gact(f1.w + f2.w + eav*wf.w, s1.w + s2.w + eav*ws.w);
        if (lane == 0)
            acct += gact(f1t + p2[128] + eav*wft, s1t + p2[PLN + 128] + eav*wst);
    }
    float* xr = xn + (size_t)n * XS;
    const float* xcr = xc + (size_t)n * XS;
    float4 xv = *(const float4*)(xcr + lane*4);
    xv.x += acc.x; xv.y += acc.y; xv.z += acc.z; xv.w += acc.w;
    *(float4*)(xr + lane*4) = xv;
    if (lane == 0) xr[128] = xcr[128] + acct;
}

// ---- pooling + head ----
__global__ void zero_pool_kernel(){
    int idx = blockIdx.x * blockDim.x + threadIdx.x;
    if (idx < NUM_GRAPHS*PLN) d_gsum[idx] = 0.f;
    if (idx < NUM_GRAPHS)     d_gcnt[idx] = 0.f;
}
__global__ __launch_bounds__(256)
void pool_kernel(const float* __restrict__ x, const int* __restrict__ batch){
    int lane = threadIdx.x & 31, warp = threadIdx.x >> 5;
    int n = blockIdx.x * 8 + warp;
    int b = batch[n];
    const float* xr = x + (size_t)n * XS;
    float4 v = *(const float4*)(xr + lane*4);
    red4(&d_gsum[b*PLN + lane*4], v);
    if (lane == 0) atomicAdd(&d_gsum[b*PLN + 128], xr[128]);
    if (lane == 1) atomicAdd(&d_gcnt[b], 1.f);
}
__global__ void head_kernel(const float* __restrict__ Wfc, const float* __restrict__ bfc,
                            const float* __restrict__ Wout, const float* __restrict__ bout,
                            float* __restrict__ out){
    int g = blockIdx.x, t = threadIdx.x;
    __shared__ float row[C];
    __shared__ float red[256];
    if (t < C) row[t] = d_gsum[g*PLN + t] / fmaxf(d_gcnt[g], 1.f);
    __syncthreads();
    for (int l = 0; l < 3; l++){
        float y = 0.f;
        if (t < C){
            #pragma unroll 4
            for (int k = 0; k < C; k++) y = fmaf(row[k], Wfc[(l*C + k)*C + t], y);
            y += bfc[l*C + t];
        }
        __syncthreads();
        if (t < C) row[t] = y;
        __syncthreads();
    }
    red[t] = (t < C) ? row[t]*Wout[t] : 0.f;
    __syncthreads();
    for (int s = 128; s > 0; s >>= 1){ if (t < s) red[t] += red[t + s]; __syncthreads(); }
    if (t == 0) out[g] = red[0] + bout[0];
}

extern "C" void kernel_launch(void* const* d_in, const int* in_sizes, int n_in,
                              void* d_out, int out_size){
    const int*   atoms = (const int*)d_in[0];
    const float* pos   = (const float*)d_in[1];
    const int*   ei    = (const int*)d_in[2];
    const int*   batch = (const int*)d_in[3];
    const float* emb   = (const float*)d_in[4];
    const float* Wf    = (const float*)d_in[5];
    const float* bf    = (const float*)d_in[6];
    const float* Ws    = (const float*)d_in[7];
    const float* bs    = (const float*)d_in[8];
    const float* Wfc   = (const float*)d_in[9];
    const float* bfc   = (const float*)d_in[10];
    const float* Wout  = (const float*)d_in[11];
    const float* bout  = (const float*)d_in[12];
    float* out = (float*)d_out;

    cudaFuncSetAttribute(node_gemm_kernel,
                         cudaFuncAttributeMaxDynamicSharedMemorySize, GSMEM);

    float *xa, *xb;
    cudaGetSymbolAddress((void**)&xa, d_xa);
    cudaGetSymbolAddress((void**)&xb, d_xb);

    pack_wbN_kernel<<<(NLAYERS*2*2*5*NPG*32 + 255)/256, 256>>>(Wf, Ws);
    pack_bph_kernel<<<(NLAYERS*2*NPG + 255)/256, 256>>>(bf, bs);
    pack_w3_kernel<<<(NLAYERS*NCOL + 255)/256, 256>>>(Wf, Ws);
    init_x_kernel<<<(NROWS*XS + 255)/256, 256>>>(atoms, pos, emb);

    // CSR build (per call, deterministic content up to segment permutation)
    zero_cnt_kernel<<<(N_NODES + 255)/256, 256>>>();
    hist_kernel<<<(N_EDGES + 255)/256, 256>>>(ei);
    scan_kernel<<<1, 1024>>>();
    scatter_kernel<<<(N_EDGES + 255)/256, 256>>>(ei, pos);

    float* cur = xa;
    float* nxt = xb;
    for (int l = 0; l < NLAYERS; l++){
        node_gemm_kernel<<<dim3(NROWS/128, 2), 512, GSMEM>>>(cur, l);
        edge_csr_kernel<<<N_NODES/8, 256>>>(cur, nxt, l);
        float* tmp = cur; cur = nxt; nxt = tmp;
    }

    zero_pool_kernel<<<(NUM_GRAPHS*PLN + 255)/256, 256>>>();
    pool_kernel<<<N_NODES/8, 256>>>(cur, batch);
    head_kernel<<<NUM_GRAPHS, 256>>>(Wfc, bfc, Wout, bout, out);
}

// round 7
// speedup vs baseline: 18.1876x; 1.0428x over previous
#include <cuda_runtime.h>
#include <cuda_bf16.h>
#include <cuda_fp16.h>
#include <cstdint>
#include <math.h>

#define N_NODES   50000
#define NROWS     50048
#define N_EDGES   800000
#define NUM_GRAPHS 256
#define C         129
#define ZDIM      259
#define NLAYERS   5
#define XS        160
#define PLN       132
#define NCOL      264
#define NPG       288
#define P2S       320     // P2h row stride in halves (640B)

// GEMM smem offsets
#define GSA    0
#define GSAL   43008
#define GSB    86016
#define GSSP   23040
#define GSBUF  46080
#define GSBI   178176
#define GSMEM  179328

__device__ __align__(16) __nv_bfloat16 d_wbN[NLAYERS*2*2*5*NPG*32];
__device__ float d_bph[NLAYERS*2*NPG];
__device__ float d_w3[NLAYERS*NCOL];
__device__ __align__(16) float d_xa[NROWS*XS];
__device__ __align__(16) float d_xb[NROWS*XS];
__device__ __align__(16) float  d_P1[(size_t)NROWS*NCOL];   // dst planes, f32
__device__ __align__(16) __half d_P2h[(size_t)NROWS*P2S];   // src planes, fp16
__device__ int   d_cnt[N_NODES];
__device__ int   d_rowptr[N_NODES + 1];
__device__ int   d_pos[N_NODES];
__device__ int   d_srcS[N_EDGES];
__device__ float d_eaS[N_EDGES];
__device__ float d_gsum[NUM_GRAPHS*PLN];
__device__ float d_gcnt[NUM_GRAPHS];

__device__ __forceinline__ uint32_t smem_u32(const void* p){
    uint32_t a;
    asm("{ .reg .u64 t; cvta.to.shared.u64 t, %1; cvt.u32.u64 %0, t; }" : "=r"(a) : "l"(p));
    return a;
}
__device__ __forceinline__ void mma16816(float* d, uint32_t a0, uint32_t a1,
                                         uint32_t a2, uint32_t a3,
                                         uint32_t b0, uint32_t b1){
    asm volatile(
        "mma.sync.aligned.m16n8k16.row.col.f32.bf16.bf16.f32 "
        "{%0,%1,%2,%3}, {%4,%5,%6,%7}, {%8,%9}, {%0,%1,%2,%3};"
        : "+f"(d[0]), "+f"(d[1]), "+f"(d[2]), "+f"(d[3])
        : "r"(a0), "r"(a1), "r"(a2), "r"(a3), "r"(b0), "r"(b1));
}
__device__ __forceinline__ void cpasync16(uint32_t s, const void* g){
    asm volatile("cp.async.cg.shared.global [%0], [%1], 16;" :: "r"(s), "l"(g));
}
__device__ __forceinline__ void red4(float* p, float4 v){
    asm volatile("red.global.add.v4.f32 [%0], {%1,%2,%3,%4};"
                 :: "l"(p), "f"(v.x), "f"(v.y), "f"(v.z), "f"(v.w) : "memory");
}
__device__ __forceinline__ float sigf(float f){
    float t;
    asm("tanh.approx.f32 %0, %1;" : "=f"(t) : "f"(0.5f * f));
    return fmaf(0.5f, t, 0.5f);
}
__device__ __forceinline__ float gact(float f, float s){
    float sp = fmaxf(s, 0.f) + __logf(1.f + __expf(-fabsf(s)));
    return sigf(f) * sp;
}

// ---- prepack ----
__global__ void pack_wbN_kernel(const float* __restrict__ Wf, const float* __restrict__ Ws){
    int idx = blockIdx.x * blockDim.x + threadIdx.x;
    if (idx >= NLAYERS*2*2*5*NPG*32) return;
    int k  = idx & 31;
    int n  = (idx >> 5) % NPG;
    int kc = (idx / (32*NPG)) % 5;
    int sp = (idx / (32*NPG*5)) & 1;
    int hf = (idx / (32*NPG*5*2)) & 1;
    int l  = idx / (32*NPG*5*2*2);
    int kg = kc*32 + k;
    float w = 0.f;
    if (n < NCOL && kg < C){
        int plane = n / PLN, j = n % PLN;
        if (j < C){
            int zi = hf ? (C + kg) : kg;
            const float* W = plane ? Ws : Wf;
            w = W[(l*ZDIM + zi)*C + j];
        }
    }
    __nv_bfloat16 hi = __float2bfloat16(w);
    d_wbN[idx] = sp ? __float2bfloat16(w - __bfloat162float(hi)) : hi;
}
__global__ void pack_bph_kernel(const float* __restrict__ bf, const float* __restrict__ bs){
    int idx = blockIdx.x * blockDim.x + threadIdx.x;
    if (idx >= NLAYERS*2*NPG) return;
    int n = idx % NPG, hf = (idx / NPG) & 1, l = idx / (2*NPG);
    float v = 0.f;
    if (hf == 0 && n < NCOL){
        int plane = n / PLN, j = n % PLN;
        if (j < C) v = plane ? bs[l*C + j] : bf[l*C + j];
    }
    d_bph[idx] = v;
}
__global__ void pack_w3_kernel(const float* __restrict__ Wf, const float* __restrict__ Ws){
    int idx = blockIdx.x * blockDim.x + threadIdx.x;
    if (idx >= NLAYERS*NCOL) return;
    int n = idx % NCOL, l = idx / NCOL;
    int plane = n / PLN, j = n % PLN;
    float v = 0.f;
    if (j < C){ const float* W = plane ? Ws : Wf; v = W[(l*ZDIM + 258)*C + j]; }
    d_w3[idx] = v;
}
__global__ void init_x_kernel(const int* __restrict__ atoms, const float* __restrict__ pos,
                              const float* __restrict__ emb){
    int idx = blockIdx.x * blockDim.x + threadIdx.x;
    if (idx >= NROWS*XS) return;
    int n = idx / XS, c = idx - n*XS;
    float v = 0.f;
    if (n < N_NODES){
        if (c < 128) v = emb[atoms[n]*128 + c];
        else if (c == 128) v = pos[n*3 + 2];
    }
    d_xa[idx] = v;
}

// ---- CSR build ----
__global__ void zero_cnt_kernel(){
    int i = blockIdx.x * blockDim.x + threadIdx.x;
    if (i < N_NODES) d_cnt[i] = 0;
}
__global__ void hist_kernel(const int* __restrict__ ei){
    int e = blockIdx.x * blockDim.x + threadIdx.x;
    if (e < N_EDGES) atomicAdd(&d_cnt[ei[N_EDGES + e]], 1);
}
__global__ void scan_kernel(){
    __shared__ int wsum[32];
    __shared__ int carry;
    int tid = threadIdx.x, lane = tid & 31, wid = tid >> 5;
    if (tid == 0) carry = 0;
    __syncthreads();
    for (int base = 0; base < N_NODES; base += 1024){
        int i = base + tid;
        int v = (i < N_NODES) ? d_cnt[i] : 0;
        int x = v;
        #pragma unroll
        for (int d = 1; d < 32; d <<= 1){
            int y = __shfl_up_sync(0xffffffffu, x, d);
            if (lane >= d) x += y;
        }
        if (lane == 31) wsum[wid] = x;
        __syncthreads();
        if (wid == 0){
            int s = wsum[lane];
            #pragma unroll
            for (int d = 1; d < 32; d <<= 1){
                int y = __shfl_up_sync(0xffffffffu, s, d);
                if (lane >= d) s += y;
            }
            wsum[lane] = s;
        }
        __syncthreads();
        int excl = x - v + (wid ? wsum[wid-1] : 0) + carry;
        if (i < N_NODES){ d_rowptr[i] = excl; d_pos[i] = excl; }
        __syncthreads();
        if (tid == 0) carry += wsum[31];
        __syncthreads();
    }
    if (threadIdx.x == 0) d_rowptr[N_NODES] = carry;
}
__global__ void scatter_kernel(const int* __restrict__ ei, const float* __restrict__ pos){
    int e = blockIdx.x * blockDim.x + threadIdx.x;
    if (e >= N_EDGES) return;
    int s = ei[e], d = ei[N_EDGES + e];
    float dx = pos[s*3]-pos[d*3], dy = pos[s*3+1]-pos[d*3+1], dz = pos[s*3+2]-pos[d*3+2];
    float eav = sqrtf(dx*dx + dy*dy + dz*dz);
    int p = atomicAdd(&d_pos[d], 1);
    d_srcS[p] = s;
    d_eaS[p] = eav;
}

// ---- node GEMM ----
__global__ __launch_bounds__(512, 1)
void node_gemm_kernel(const float* __restrict__ xc, int layer){
    extern __shared__ __align__(16) char smem[];
    uint32_t sb = smem_u32(smem);
    int tid = threadIdx.x, lane = tid & 31, wid = tid >> 5;
    int r0 = lane >> 2, tin = lane & 3;
    int warpM = wid & 3, warpN = wid >> 2;
    int m0 = blockIdx.x * 128;
    int hf = blockIdx.y;

    const __nv_bfloat16* wbase = d_wbN + (size_t)((layer*2 + hf)*2) * 5*NPG*32;

    #pragma unroll
    for (int pc = 0; pc < 2; pc++){
        for (int i = tid; i < 2304; i += 512){
            int sp = i / 1152, rr = i % 1152, n = rr >> 2, kv = rr & 3;
            const void* g = wbase + ((size_t)sp*5 + pc)*NPG*32 + n*32 + kv*8;
            cpasync16(sb + GSB + pc*GSBUF + sp*GSSP + n*80 + kv*16, g);
        }
        asm volatile("cp.async.commit_group;" ::: "memory");
    }
    float* biS = (float*)(smem + GSBI);
    for (int i = tid; i < NPG; i += 512) biS[i] = d_bph[(layer*2 + hf)*NPG + i];

    {
        int row = tid >> 2, q = tid & 3;
        const float4* xr = (const float4*)(xc + (size_t)(m0 + row)*XS) + q*10;
        char* arow = smem + GSA + row*336 + q*80;
        #pragma unroll
        for (int j = 0; j < 10; j++){
            float4 v = xr[j];
            __nv_bfloat16 hx = __float2bfloat16(v.x), hy = __float2bfloat16(v.y);
            __nv_bfloat16 hz = __float2bfloat16(v.z), hw = __float2bfloat16(v.w);
            __nv_bfloat162 h0(hx, hy), h1(hz, hw);
            __nv_bfloat162 l0(__float2bfloat16(v.x - __bfloat162float(hx)),
                              __float2bfloat16(v.y - __bfloat162float(hy)));
            __nv_bfloat162 l1(__float2bfloat16(v.z - __bfloat162float(hz)),
                              __float2bfloat16(v.w - __bfloat162float(hw)));
            *(uint2*)(arow + j*8)        = make_uint2(*(uint32_t*)&h0, *(uint32_t*)&h1);
            *(uint2*)(arow + GSAL + j*8) = make_uint2(*(uint32_t*)&l0, *(uint32_t*)&l1);
        }
    }

    float acc[2][9][4];
    #pragma unroll
    for (int a = 0; a < 2; a++)
        #pragma unroll
        for (int b = 0; b < 9; b++)
            #pragma unroll
            for (int c = 0; c < 4; c++) acc[a][b][c] = 0.f;

    uint32_t aoff = (uint32_t)((warpM*32 + r0)*336 + tin*4);
    uint32_t boff = (uint32_t)((warpN*72 + r0)*80 + tin*4);

    for (int sc = 0; sc < 5; sc++){
        int buf = sc & 1;
        if (sc == 4) asm volatile("cp.async.wait_group 0;" ::: "memory");
        else         asm volatile("cp.async.wait_group 1;" ::: "memory");
        __syncthreads();
        const char* bbuf = smem + GSB + buf*GSBUF;
        #pragma unroll
        for (int ks = 0; ks < 2; ks++){
            uint32_t ka = (uint32_t)(sc*32 + ks*16)*2;
            const char* ap = smem + GSA + aoff + ka;
            uint32_t ah[2][4], al[2][4];
            #pragma unroll
            for (int mt = 0; mt < 2; mt++){
                const char* p = ap + mt*5376;
                ah[mt][0] = *(const uint32_t*)(p);
                ah[mt][1] = *(const uint32_t*)(p + 2688);
                ah[mt][2] = *(const uint32_t*)(p + 16);
                ah[mt][3] = *(const uint32_t*)(p + 2704);
                const char* q = p + GSAL;
                al[mt][0] = *(const uint32_t*)(q);
                al[mt][1] = *(const uint32_t*)(q + 2688);
                al[mt][2] = *(const uint32_t*)(q + 16);
                al[mt][3] = *(const uint32_t*)(q + 2704);
            }
            uint32_t kb = (uint32_t)ks*32;
            #pragma unroll
            for (int nt = 0; nt < 9; nt++){
                const char* bp = bbuf + boff + nt*640 + kb;
                uint32_t bh0 = *(const uint32_t*)(bp);
                uint32_t bh1 = *(const uint32_t*)(bp + 16);
                uint32_t bl0 = *(const uint32_t*)(bp + GSSP);
                uint32_t bl1 = *(const uint32_t*)(bp + GSSP + 16);
                mma16816(acc[0][nt], ah[0][0], ah[0][1], ah[0][2], ah[0][3], bh0, bh1);
                mma16816(acc[1][nt], ah[1][0], ah[1][1], ah[1][2], ah[1][3], bh0, bh1);
                mma16816(acc[0][nt], al[0][0], al[0][1], al[0][2], al[0][3], bh0, bh1);
                mma16816(acc[1][nt], al[1][0], al[1][1], al[1][2], al[1][3], bh0, bh1);
                mma16816(acc[0][nt], ah[0][0], ah[0][1], ah[0][2], ah[0][3], bl0, bl1);
                mma16816(acc[1][nt], ah[1][0], ah[1][1], ah[1][2], ah[1][3], bl0, bl1);
            }
        }
        __syncthreads();
        if (sc < 3){
            int nc = sc + 2;
            for (int i = tid; i < 2304; i += 512){
                int sp = i / 1152, rr = i % 1152, n = rr >> 2, kv = rr & 3;
                const void* g = wbase + ((size_t)sp*5 + nc)*NPG*32 + n*32 + kv*8;
                cpasync16(sb + GSB + buf*GSBUF + sp*GSSP + n*80 + kv*16, g);
            }
            asm volatile("cp.async.commit_group;" ::: "memory");
        }
    }

    #pragma unroll
    for (int mt = 0; mt < 2; mt++){
        #pragma unroll
        for (int nt = 0; nt < 9; nt++){
            int col = warpN*72 + nt*8 + tin*2;
            if (col >= NCOL) continue;
            float b0 = biS[col], b1 = biS[col + 1];
            #pragma unroll
            for (int h = 0; h < 2; h++){
                int row = m0 + warpM*32 + mt*16 + r0 + h*8;
                float v0 = acc[mt][nt][2*h] + b0;
                float v1 = acc[mt][nt][2*h+1] + b1;
                if (hf == 0){
                    *(float2*)(d_P1 + (size_t)row*NCOL + col) = make_float2(v0, v1);
                } else {
                    *(__half2*)(d_P2h + (size_t)row*P2S + col) = __floats2half2_rn(v0, v1);
                }
            }
        }
    }
}

// ---- edge phase: warp-per-node CSR, fp16 src gather, tanh sigmoid ----
__global__ __launch_bounds__(256)
void edge_csr_kernel(const float* __restrict__ xc, float* __restrict__ xn, int layer){
    int lane = threadIdx.x & 31, warp = threadIdx.x >> 5;
    int n = blockIdx.x * 8 + warp;
    const float* w3 = d_w3 + layer * NCOL;
    float4 wf = *(const float4*)(w3 + lane*4);
    float4 ws = *(const float4*)(w3 + PLN + lane*4);
    const float* p1 = d_P1 + (size_t)n * NCOL;
    float4 f1 = *(const float4*)(p1 + lane*4);
    float4 s1 = *(const float4*)(p1 + PLN + lane*4);
    float f1t = 0.f, s1t = 0.f, wft = 0.f, wst = 0.f;
    if (lane == 0){
        f1t = p1[128]; s1t = p1[PLN + 128];
        wft = w3[128]; wst = w3[PLN + 128];
    }
    int beg = d_rowptr[n], end = d_rowptr[n + 1];
    float4 acc = make_float4(0.f, 0.f, 0.f, 0.f);
    float acct = 0.f;
    for (int i = beg; i < end; i++){
        int src = d_srcS[i];
        float eav = d_eaS[i];
        const __half* p2 = d_P2h + (size_t)src * P2S;
        uint2 fu = *(const uint2*)(p2 + lane*4);
        uint2 su = *(const uint2*)(p2 + PLN + lane*4);
        float2 fa = __half22float2(*(__half2*)&fu.x);
        float2 fb = __half22float2(*(__half2*)&fu.y);
        float2 sa = __half22float2(*(__half2*)&su.x);
        float2 sb = __half22float2(*(__half2*)&su.y);
        acc.x += gact(f1.x + fa.x + eav*wf.x, s1.x + sa.x + eav*ws.x);
        acc.y += gact(f1.y + fa.y + eav*wf.y, s1.y + sa.y + eav*ws.y);
        acc.z += gact(f1.z + fb.x + eav*wf.z, s1.z + sb.x + eav*ws.z);
        acc.w += gact(f1.w + fb.y + eav*wf.w, s1.w + sb.y + eav*ws.w);
        if (lane == 0)
            acct += gact(f1t + __half2float(p2[128]) + eav*wft,
                         s1t + __half2float(p2[PLN + 128]) + eav*wst);
    }
    float* xr = xn + (size_t)n * XS;
    const float* xcr = xc + (size_t)n * XS;
    float4 xv = *(const float4*)(xcr + lane*4);
    xv.x += acc.x; xv.y += acc.y; xv.z += acc.z; xv.w += acc.w;
    *(float4*)(xr + lane*4) = xv;
    if (lane == 0) xr[128] = xcr[128] + acct;
}

// ---- pooling + head ----
__global__ void zero_pool_kernel(){
    int idx = blockIdx.x * blockDim.x + threadIdx.x;
    if (idx < NUM_GRAPHS*PLN) d_gsum[idx] = 0.f;
    if (idx < NUM_GRAPHS)     d_gcnt[idx] = 0.f;
}
__global__ __launch_bounds__(256)
void pool_kernel(const float* __restrict__ x, const int* __restrict__ batch){
    int lane = threadIdx.x & 31, warp = threadIdx.x >> 5;
    int n = blockIdx.x * 8 + warp;
    int b = batch[n];
    const float* xr = x + (size_t)n * XS;
    float4 v = *(const float4*)(xr + lane*4);
    red4(&d_gsum[b*PLN + lane*4], v);
    if (lane == 0) atomicAdd(&d_gsum[b*PLN + 128], xr[128]);
    if (lane == 1) atomicAdd(&d_gcnt[b], 1.f);
}
__global__ void head_kernel(const float* __restrict__ Wfc, const float* __restrict__ bfc,
                            const float* __restrict__ Wout, const float* __restrict__ bout,
                            float* __restrict__ out){
    int g = blockIdx.x, t = threadIdx.x;
    __shared__ float row[C];
    __shared__ float red[256];
    if (t < C) row[t] = d_gsum[g*PLN + t] / fmaxf(d_gcnt[g], 1.f);
    __syncthreads();
    for (int l = 0; l < 3; l++){
        float y = 0.f;
        if (t < C){
            #pragma unroll 4
            for (int k = 0; k < C; k++) y = fmaf(row[k], Wfc[(l*C + k)*C + t], y);
            y += bfc[l*C + t];
        }
        __syncthreads();
        if (t < C) row[t] = y;
        __syncthreads();
    }
    red[t] = (t < C) ? row[t]*Wout[t] : 0.f;
    __syncthreads();
    for (int s = 128; s > 0; s >>= 1){ if (t < s) red[t] += red[t + s]; __syncthreads(); }
    if (t == 0) out[g] = red[0] + bout[0];
}

extern "C" void kernel_launch(void* const* d_in, const int* in_sizes, int n_in,
                              void* d_out, int out_size){
    const int*   atoms = (const int*)d_in[0];
    const float* pos   = (const float*)d_in[1];
    const int*   ei    = (const int*)d_in[2];
    const int*   batch = (const int*)d_in[3];
    const float* emb   = (const float*)d_in[4];
    const float* Wf    = (const float*)d_in[5];
    const float* bf    = (const float*)d_in[6];
    const float* Ws    = (const float*)d_in[7];
    const float* bs    = (const float*)d_in[8];
    const float* Wfc   = (const float*)d_in[9];
    const float* bfc   = (const float*)d_in[10];
    const float* Wout  = (const float*)d_in[11];
    const float* bout  = (const float*)d_in[12];
    float* out = (float*)d_out;

    cudaFuncSetAttribute(node_gemm_kernel,
                         cudaFuncAttributeMaxDynamicSharedMemorySize, GSMEM);

    float *xa, *xb;
    cudaGetSymbolAddress((void**)&xa, d_xa);
    cudaGetSymbolAddress((void**)&xb, d_xb);

    pack_wbN_kernel<<<(NLAYERS*2*2*5*NPG*32 + 255)/256, 256>>>(Wf, Ws);
    pack_bph_kernel<<<(NLAYERS*2*NPG + 255)/256, 256>>>(bf, bs);
    pack_w3_kernel<<<(NLAYERS*NCOL + 255)/256, 256>>>(Wf, Ws);
    init_x_kernel<<<(NROWS*XS + 255)/256, 256>>>(atoms, pos, emb);

    zero_cnt_kernel<<<(N_NODES + 255)/256, 256>>>();
    hist_kernel<<<(N_EDGES + 255)/256, 256>>>(ei);
    scan_kernel<<<1, 1024>>>();
    scatter_kernel<<<(N_EDGES + 255)/256, 256>>>(ei, pos);

    float* cur = xa;
    float* nxt = xb;
    for (int l = 0; l < NLAYERS; l++){
        node_gemm_kernel<<<dim3(NROWS/128, 2), 512, GSMEM>>>(cur, l);
        edge_csr_kernel<<<N_NODES/8, 256>>>(cur, nxt, l);
        float* tmp = cur; cur = nxt; nxt = tmp;
    }

    zero_pool_kernel<<<(NUM_GRAPHS*PLN + 255)/256, 256>>>();
    pool_kernel<<<N_NODES/8, 256>>>(cur, batch);
    head_kernel<<<NUM_GRAPHS, 256>>>(Wfc, bfc, Wout, bout, out);
}